// round 15
// baseline (speedup 1.0000x reference)
#include <cuda_runtime.h>
#include <cuda_bf16.h>
#include <math.h>
#include <stdint.h>

#define BB   8
#define SS_  512
#define LL   6
#define HH   8
#define DD   512
#define DKK  64
#define DFFN 2048
#define MS   (BB*SS_)
#define HD   (HH*DKK)

typedef __nv_bfloat16 bf16;

// ---------------- scratch ----------------
__device__ __align__(1024) bf16  g_W  [132120576];
__device__ __align__(1024) bf16  g_Ax [(long)MS*1536];
__device__ __align__(1024) bf16  g_Ae [(long)MS*1536];
__device__ __align__(1024) bf16  g_Aff[(long)MS*6144];
__device__ __align__(1024) bf16  g_Ao [(long)MS*1536];
__device__ __align__(1024) bf16  g_Aq [(long)64*512*192];
__device__ __align__(1024) bf16  g_Bk [(long)64*512*192];
__device__ __align__(1024) bf16  g_Bv [(long)64*64*1536];
__device__ __align__(1024) float g_qkv[(long)MS*1536];
__device__ __align__(1024) float g_x [MS*DD];
__device__ __align__(1024) float g_y [MS*DD];
__device__ __align__(1024) float g_a [MS*DD];
__device__ __align__(1024) float g_pe[SS_*DD];

// ---------------- helpers ----------------
__device__ __forceinline__ uint32_t smem_u32(const void* p) {
    uint32_t a;
    asm("{ .reg .u64 t; cvta.to.shared.u64 t, %1; cvt.u32.u64 %0, t; }" : "=r"(a) : "l"(p));
    return a;
}
#define SW128(o) ((o) ^ (((o) >> 3) & 0x70))

__device__ __forceinline__ void cp_async16(uint32_t daddr, const void* gptr) {
    asm volatile("cp.async.cg.shared.global [%0], [%1], 16;" :: "r"(daddr), "l"(gptr));
}
__device__ __forceinline__ void cp_commit() {
    asm volatile("cp.async.commit_group;" ::: "memory");
}
__device__ __forceinline__ void cp_wait(int w) {
    switch (w) {
    case 0: asm volatile("cp.async.wait_group 0;" ::: "memory"); break;
    case 1: asm volatile("cp.async.wait_group 1;" ::: "memory"); break;
    case 2: asm volatile("cp.async.wait_group 2;" ::: "memory"); break;
    default: asm volatile("cp.async.wait_group 3;" ::: "memory"); break;
    }
}
__device__ __forceinline__ void ldmx4(uint32_t* r, uint32_t addr) {
    asm volatile("ldmatrix.sync.aligned.m8n8.x4.shared.b16 {%0,%1,%2,%3}, [%4];"
                 : "=r"(r[0]), "=r"(r[1]), "=r"(r[2]), "=r"(r[3]) : "r"(addr));
}
__device__ __forceinline__ void mma16816(float* d, const uint32_t* a, const uint32_t* b) {
    asm volatile("mma.sync.aligned.m16n8k16.row.col.f32.bf16.bf16.f32 "
                 "{%0,%1,%2,%3}, {%4,%5,%6,%7}, {%8,%9}, {%0,%1,%2,%3};"
                 : "+f"(d[0]), "+f"(d[1]), "+f"(d[2]), "+f"(d[3])
                 : "r"(a[0]), "r"(a[1]), "r"(a[2]), "r"(a[3]), "r"(b[0]), "r"(b[1]));
}
__device__ __forceinline__ void split2(float v, bf16& hi, bf16& lo) {
    hi = __float2bfloat16(v);
    lo = __float2bfloat16(v - __bfloat162float(hi));
}
__device__ __forceinline__ uint32_t pack_hi2(float a, float b, float& ra, float& rb) {
    __nv_bfloat162 h;
    h.x = __float2bfloat16(a); h.y = __float2bfloat16(b);
    ra = a - __bfloat162float(h.x);
    rb = b - __bfloat162float(h.y);
    return *(uint32_t*)&h;
}
__device__ __forceinline__ uint32_t pack_bf2(float a, float b) {
    __nv_bfloat162 h;
    h.x = __float2bfloat16(a); h.y = __float2bfloat16(b);
    return *(uint32_t*)&h;
}

// ---------------- GEMM (4 warps; STAGES-deep cp.async pipeline) ----------------
template<int BN, int WM, int WN, int THREADS, int STAGES>
__global__ __launch_bounds__(THREADS, 2)
void gemm_mma(const bf16* __restrict__ A, const bf16* __restrict__ B,
              float* __restrict__ C, const float* __restrict__ bias,
              bf16* __restrict__ Cs, int nreg,
              int Kp, int ldc, int relu)
{
    constexpr int BM = 128;
    constexpr int ASZ = BM*128, BSZ = BN*128, STG = ASZ + BSZ;
    constexpr int MT = WM/16, NT = WN/8, WCOLS = BN/WN;
    const int ldcs = 3*nreg;

    extern __shared__ char smraw[];
    char* sm = (char*)(((uintptr_t)smraw + 1023) & ~(uintptr_t)1023);

    const int tid = threadIdx.x;
    const int wid = tid >> 5, lane = tid & 31;
    const int wm = (wid / WCOLS) * WM;
    const int wn = (wid % WCOLS) * WN;

    const long bm = (long)blockIdx.y * BM;
    const long bn = (long)blockIdx.x * BN;
    const bf16* Ag = A + bm*(long)Kp;
    const bf16* Bg = B + bn*(long)Kp;
    const int nc = Kp >> 6;

    float acc[MT][NT][4];
    #pragma unroll
    for (int i = 0; i < MT; i++)
        #pragma unroll
        for (int j = 0; j < NT; j++)
            #pragma unroll
            for (int q = 0; q < 4; q++) acc[i][j][q] = 0.f;

    auto issue = [&](int c) {
        char* sa = sm + (c % STAGES)*STG;
        char* sb = sa + ASZ;
        uint32_t sa32 = smem_u32(sa), sb32 = smem_u32(sb);
        #pragma unroll
        for (int p = 0; p < BM*8/THREADS; p++) {
            int idx = tid + p*THREADS;
            int row = idx >> 3, ch = idx & 7;
            cp_async16(sa32 + SW128((uint32_t)(row*128 + ch*16)),
                       Ag + (long)row*Kp + (long)c*64 + ch*8);
        }
        #pragma unroll
        for (int p = 0; p < BN*8/THREADS; p++) {
            int idx = tid + p*THREADS;
            int row = idx >> 3, ch = idx & 7;
            cp_async16(sb32 + SW128((uint32_t)(row*128 + ch*16)),
                       Bg + (long)row*Kp + (long)c*64 + ch*8);
        }
        cp_commit();
    };

    #pragma unroll
    for (int s = 0; s < STAGES; s++)
        if (s < nc) issue(s);

    for (int c = 0; c < nc; c++) {
        int rem = nc - 1 - c;
        cp_wait(rem < STAGES-1 ? rem : STAGES-1);
        __syncthreads();

        char* sa = sm + (c % STAGES)*STG;
        char* sb = sa + ASZ;
        uint32_t abase = smem_u32(sa), bbase = smem_u32(sb);

        #pragma unroll
        for (int ks = 0; ks < 4; ks++) {
            uint32_t af[MT][4], bfr[NT][2];
            #pragma unroll
            for (int i = 0; i < MT; i++) {
                uint32_t off = (uint32_t)((wm + i*16 + (lane & 15))*128 + ks*32 + (lane >> 4)*16);
                ldmx4(af[i], abase + SW128(off));
            }
            #pragma unroll
            for (int j = 0; j < NT/2; j++) {
                uint32_t off = (uint32_t)((wn + j*16 + (lane & 15))*128 + ks*32 + (lane >> 4)*16);
                uint32_t r[4];
                ldmx4(r, bbase + SW128(off));
                bfr[2*j][0]   = r[0]; bfr[2*j][1]   = r[2];
                bfr[2*j+1][0] = r[1]; bfr[2*j+1][1] = r[3];
            }
            #pragma unroll
            for (int i = 0; i < MT; i++)
                #pragma unroll
                for (int j = 0; j < NT; j++)
                    mma16816(acc[i][j], af[i], bfr[j]);
        }
        __syncthreads();
        if (c + STAGES < nc) issue(c + STAGES);
    }

    #pragma unroll
    for (int i = 0; i < MT; i++) {
        #pragma unroll
        for (int j = 0; j < NT; j++) {
            long r0  = bm + wm + i*16 + (lane >> 2);
            int  col = (int)bn + wn + j*8 + (lane & 3)*2;
            float2 v0 = make_float2(acc[i][j][0], acc[i][j][1]);
            float2 v1 = make_float2(acc[i][j][2], acc[i][j][3]);
            if (bias) {
                float2 bb = *(const float2*)(bias + col);
                v0.x += bb.x; v0.y += bb.y; v1.x += bb.x; v1.y += bb.y;
            }
            if (relu) {
                v0.x = fmaxf(v0.x, 0.f); v0.y = fmaxf(v0.y, 0.f);
                v1.x = fmaxf(v1.x, 0.f); v1.y = fmaxf(v1.y, 0.f);
            }
            if (C) {
                *(float2*)(C + r0*(long)ldc + col)     = v0;
                *(float2*)(C + (r0+8)*(long)ldc + col) = v1;
            }
            if (Cs) {
                bf16* p0 = Cs + r0*(long)ldcs + col;
                bf16* p1 = Cs + (r0+8)*(long)ldcs + col;
                __nv_bfloat162 h, l;
                h.x = __float2bfloat16(v0.x);
                h.y = __float2bfloat16(v0.y);
                l.x = __float2bfloat16(v0.x - __bfloat162float(h.x));
                l.y = __float2bfloat16(v0.y - __bfloat162float(h.y));
                *(__nv_bfloat162*)(p0)          = h;
                *(__nv_bfloat162*)(p0 + nreg)   = h;
                *(__nv_bfloat162*)(p0 + 2*nreg) = l;
                h.x = __float2bfloat16(v1.x);
                h.y = __float2bfloat16(v1.y);
                l.x = __float2bfloat16(v1.x - __bfloat162float(h.x));
                l.y = __float2bfloat16(v1.y - __bfloat162float(h.y));
                *(__nv_bfloat162*)(p1)          = h;
                *(__nv_bfloat162*)(p1 + nreg)   = h;
                *(__nv_bfloat162*)(p1 + 2*nreg) = l;
            }
        }
    }
}

// ---------------- fused flash attention (causal heavy-first) ----------------
__global__ __launch_bounds__(256, 1)
void flash_attn(const bf16* __restrict__ Aq, const bf16* __restrict__ Bk,
                const bf16* __restrict__ Bv, bf16* __restrict__ Ao, int causal)
{
    extern __shared__ char smraw[];
    uint32_t smQ = (smem_u32(smraw) + 1023) & ~1023u;
    uint32_t smK = smQ + 49152;
    uint32_t smV = smQ + 49152 + 49152;

    const int tid = threadIdx.x, wid = tid >> 5, lane = tid & 31;
    const int qt = causal ? (3 - blockIdx.x) : blockIdx.x;
    const int z = blockIdx.y;
    const int qbase = qt*128;
    const int nt = causal ? (2*qt + 2) : 8;

    {
        const bf16* qsrc = Aq + ((long)z*512 + qbase)*192;
        for (int i = tid; i < 3072; i += 256) {
            int ch = i >> 10, rem = i & 1023;
            int row = rem >> 3, seg = rem & 7;
            cp_async16(smQ + ch*16384 + SW128((uint32_t)(row*128 + seg*16)),
                       qsrc + (long)row*192 + ch*64 + seg*8);
        }
    }
    auto load_kv = [&](int t, int st) {
        uint32_t kst = smK + st*24576;
        uint32_t vst = smV + st*16384;
        const bf16* ksrc = Bk + ((long)z*512 + t*64)*192;
        for (int i = tid; i < 1536; i += 256) {
            int ch = i >> 9, rem = i & 511;
            int row = rem >> 3, seg = rem & 7;
            cp_async16(kst + ch*8192 + SW128((uint32_t)(row*128 + seg*16)),
                       ksrc + (long)row*192 + ch*64 + seg*8);
        }
        const bf16* vsrc = Bv + (long)z*64*1536;
        for (int i = tid; i < 1024; i += 256) {
            int hl = i >> 9, rem = i & 511;
            int dk = rem >> 3, seg = rem & 7;
            cp_async16(vst + hl*8192 + SW128((uint32_t)(dk*128 + seg*16)),
                       vsrc + (long)dk*1536 + hl*512 + t*64 + seg*8);
        }
    };

    load_kv(0, 0); cp_commit();
    if (nt > 1) { load_kv(1, 1); cp_commit(); }

    float m0 = -1e30f, m1 = -1e30f, l0 = 0.f, l1 = 0.f;
    float o[8][4];
    #pragma unroll
    for (int j = 0; j < 8; j++)
        #pragma unroll
        for (int q = 0; q < 4; q++) o[j][q] = 0.f;

    const int r0g = qbase + wid*16 + (lane >> 2);
    const int r1g = r0g + 8;

    for (int t = 0; t < nt; t++) {
        if (t + 1 < nt) asm volatile("cp.async.wait_group 1;" ::: "memory");
        else            asm volatile("cp.async.wait_group 0;" ::: "memory");
        __syncthreads();

        uint32_t kst = smK + (t & 1)*24576;
        uint32_t vst = smV + (t & 1)*16384;

        float sf[8][4];
        #pragma unroll
        for (int j = 0; j < 8; j++)
            #pragma unroll
            for (int q = 0; q < 4; q++) sf[j][q] = 0.f;

        #pragma unroll
        for (int kc = 0; kc < 12; kc++) {
            uint32_t af[4];
            ldmx4(af, smQ + (kc >> 2)*16384 +
                  SW128((uint32_t)((wid*16 + (lane & 15))*128 + (kc & 3)*32 + (lane >> 4)*16)));
            #pragma unroll
            for (int j = 0; j < 4; j++) {
                uint32_t r[4];
                ldmx4(r, kst + (kc >> 2)*8192 +
                      SW128((uint32_t)((j*16 + (lane & 15))*128 + (kc & 3)*32 + (lane >> 4)*16)));
                uint32_t b0[2] = {r[0], r[2]}, b1[2] = {r[1], r[3]};
                mma16816(sf[2*j],   af, b0);
                mma16816(sf[2*j+1], af, b1);
            }
        }

        if (causal) {
            #pragma unroll
            for (int j = 0; j < 8; j++) {
                int c0 = t*64 + j*8 + (lane & 3)*2;
                if (c0     > r0g) sf[j][0] = -1e30f;
                if (c0 + 1 > r0g) sf[j][1] = -1e30f;
                if (c0     > r1g) sf[j][2] = -1e30f;
                if (c0 + 1 > r1g) sf[j][3] = -1e30f;
            }
        }

        float tm0 = -1e30f, tm1 = -1e30f;
        #pragma unroll
        for (int j = 0; j < 8; j++) {
            tm0 = fmaxf(tm0, fmaxf(sf[j][0], sf[j][1]));
            tm1 = fmaxf(tm1, fmaxf(sf[j][2], sf[j][3]));
        }
        tm0 = fmaxf(tm0, __shfl_xor_sync(0xffffffffu, tm0, 1));
        tm0 = fmaxf(tm0, __shfl_xor_sync(0xffffffffu, tm0, 2));
        tm1 = fmaxf(tm1, __shfl_xor_sync(0xffffffffu, tm1, 1));
        tm1 = fmaxf(tm1, __shfl_xor_sync(0xffffffffu, tm1, 2));
        float mn0 = fmaxf(m0, tm0), mn1 = fmaxf(m1, tm1);
        float al0 = __expf(m0 - mn0), al1 = __expf(m1 - mn1);
        m0 = mn0; m1 = mn1;

        float rs0 = 0.f, rs1 = 0.f;
        #pragma unroll
        for (int j = 0; j < 8; j++) {
            float s0 = sf[j][0], s1 = sf[j][1], s2 = sf[j][2], s3 = sf[j][3];
            float p0 = (s0 > -1e29f) ? __expf(s0 - mn0) : 0.f;
            float p1 = (s1 > -1e29f) ? __expf(s1 - mn0) : 0.f;
            float p2 = (s2 > -1e29f) ? __expf(s2 - mn1) : 0.f;
            float p3 = (s3 > -1e29f) ? __expf(s3 - mn1) : 0.f;
            sf[j][0] = p0; sf[j][1] = p1; sf[j][2] = p2; sf[j][3] = p3;
            rs0 += p0 + p1; rs1 += p2 + p3;
        }
        rs0 += __shfl_xor_sync(0xffffffffu, rs0, 1);
        rs0 += __shfl_xor_sync(0xffffffffu, rs0, 2);
        rs1 += __shfl_xor_sync(0xffffffffu, rs1, 1);
        rs1 += __shfl_xor_sync(0xffffffffu, rs1, 2);
        l0 = l0*al0 + rs0;
        l1 = l1*al1 + rs1;
        #pragma unroll
        for (int j = 0; j < 8; j++) {
            o[j][0] *= al0; o[j][1] *= al0;
            o[j][2] *= al1; o[j][3] *= al1;
        }

        #pragma unroll
        for (int kc = 0; kc < 4; kc++) {
            float ra, rb;
            uint32_t ph[4], pl[4];
            ph[0] = pack_hi2(sf[2*kc][0],   sf[2*kc][1],   ra, rb); pl[0] = pack_bf2(ra, rb);
            ph[1] = pack_hi2(sf[2*kc][2],   sf[2*kc][3],   ra, rb); pl[1] = pack_bf2(ra, rb);
            ph[2] = pack_hi2(sf[2*kc+1][0], sf[2*kc+1][1], ra, rb); pl[2] = pack_bf2(ra, rb);
            ph[3] = pack_hi2(sf[2*kc+1][2], sf[2*kc+1][3], ra, rb); pl[3] = pack_bf2(ra, rb);
            #pragma unroll
            for (int j = 0; j < 4; j++) {
                uint32_t off = SW128((uint32_t)((j*16 + (lane & 15))*128 + kc*32 + (lane >> 4)*16));
                uint32_t rh[4], rl[4];
                ldmx4(rh, vst + off);
                ldmx4(rl, vst + 8192 + off);
                uint32_t bh0[2] = {rh[0], rh[2]}, bh1[2] = {rh[1], rh[3]};
                uint32_t bl0[2] = {rl[0], rl[2]}, bl1[2] = {rl[1], rl[3]};
                mma16816(o[2*j],   ph, bh0); mma16816(o[2*j+1], ph, bh1);
                mma16816(o[2*j],   ph, bl0); mma16816(o[2*j+1], ph, bl1);
                mma16816(o[2*j],   pl, bh0); mma16816(o[2*j+1], pl, bh1);
            }
        }

        __syncthreads();
        if (t + 2 < nt) { load_kv(t + 2, t & 1); cp_commit(); }
    }

    float i0 = 1.f / l0, i1 = 1.f / l1;
    long row0 = (long)(z >> 3)*512 + qbase + wid*16 + (lane >> 2);
    long row1 = row0 + 8;
    int colb = (z & 7)*64 + (lane & 3)*2;
    #pragma unroll
    for (int j = 0; j < 8; j++) {
        int c = colb + j*8;
        float v0 = o[j][0]*i0, v1 = o[j][1]*i0;
        float v2 = o[j][2]*i1, v3 = o[j][3]*i1;
        __nv_bfloat162 h, l;
        h.x = __float2bfloat16(v0); h.y = __float2bfloat16(v1);
        l.x = __float2bfloat16(v0 - __bfloat162float(h.x));
        l.y = __float2bfloat16(v1 - __bfloat162float(h.y));
        bf16* p0 = Ao + row0*1536 + c;
        *(__nv_bfloat162*)(p0)        = h;
        *(__nv_bfloat162*)(p0 + 512)  = h;
        *(__nv_bfloat162*)(p0 + 1024) = l;
        h.x = __float2bfloat16(v2); h.y = __float2bfloat16(v3);
        l.x = __float2bfloat16(v2 - __bfloat162float(h.x));
        l.y = __float2bfloat16(v3 - __bfloat162float(h.y));
        bf16* p1 = Ao + row1*1536 + c;
        *(__nv_bfloat162*)(p1)        = h;
        *(__nv_bfloat162*)(p1 + 512)  = h;
        *(__nv_bfloat162*)(p1 + 1024) = l;
    }
}

// ---------------- weight pack (layer-batched via ol) ----------------
__global__ void pack_BT(const float* __restrict__ src, bf16* __restrict__ out,
                        int rows, int cols, int ld, long s1, long s2, int zdiv, long ol)
{
    __shared__ float t[32][33];
    long z  = blockIdx.z;
    long zq = z / zdiv, zr = z % zdiv;
    const float* s = src + zq*s1 + zr*s2;
    bf16* o = out + zq*ol + zr*((long)cols*3L*rows);
    int k0 = blockIdx.x*32, n0 = blockIdx.y*32;
    int tx = threadIdx.x, ty = threadIdx.y;
    #pragma unroll
    for (int i = 0; i < 32; i += 8)
        t[ty+i][tx] = s[(long)(k0+ty+i)*ld + n0 + tx];
    __syncthreads();
    const long K3 = 3L*rows;
    #pragma unroll
    for (int i = 0; i < 32; i += 8) {
        float v = t[tx][ty+i];
        bf16 hi, lo; split2(v, hi, lo);
        long ob = (long)(n0 + ty + i)*K3 + k0 + tx;
        o[ob] = hi; o[ob + rows] = lo; o[ob + 2L*rows] = hi;
    }
}

// ---------------- merged attention operand pack ----------------
__global__ void pack_att(const float* __restrict__ qsrc, int qld,
                         const float* __restrict__ kvsrc, int kvld,
                         bf16* __restrict__ Aq, bf16* __restrict__ Bk,
                         bf16* __restrict__ Bv)
{
    __shared__ float t[32][33];
    int bid = blockIdx.x, tid = threadIdx.x;
    if (bid < 8192) {
        long idx = (long)bid*256 + tid;
        int kk = (int)(idx & 63);
        int s  = (int)((idx >> 6) & 511);
        int z  = (int)(idx >> 15);
        int b = z >> 3, h = z & 7;
        long srow = (long)(b*512 + s);
        float qv = qsrc[srow*qld + h*64 + kk] * 0.125f;
        float kv = kvsrc[srow*kvld + h*64 + kk];
        long ob = ((long)z*512 + s)*192;
        bf16 hi, lo;
        split2(qv, hi, lo); Aq[ob+kk] = hi; Aq[ob+64+kk] = hi; Aq[ob+128+kk] = lo;
        split2(kv, hi, lo); Bk[ob+kk] = hi; Bk[ob+64+kk] = lo; Bk[ob+128+kk] = hi;
    } else {
        int vb = bid - 8192;
        int gx = vb & 15, gy = (vb >> 4) & 1, z = vb >> 5;
        int k0 = gx*32, n0 = gy*32;
        int tx = tid & 31, ty = tid >> 5;
        const float* s = kvsrc + 512 + (long)(z >> 3)*(512L*kvld) + (z & 7)*64;
        #pragma unroll
        for (int i = 0; i < 32; i += 8)
            t[ty+i][tx] = s[(long)(k0+ty+i)*kvld + n0 + tx];
        __syncthreads();
        #pragma unroll
        for (int i = 0; i < 32; i += 8) {
            float v = t[tx][ty+i];
            bf16 hi, lo; split2(v, hi, lo);
            long ob = ((long)z*64 + n0 + ty + i)*1536 + k0 + tx;
            Bv[ob] = hi; Bv[ob + 512] = lo;
        }
    }
}

// ---------------- elementwise ----------------
__global__ void add_ln2(const float* __restrict__ x, const float* __restrict__ a,
                        const float* __restrict__ g, const float* __restrict__ b,
                        float* __restrict__ out, bf16* __restrict__ As)
{
    long row = blockIdx.x;
    int tid = threadIdx.x;
    const float* xr = x + row*DD;
    const float* ar = a + row*DD;
    float v0 = xr[tid]     + ar[tid];
    float v1 = xr[tid+256] + ar[tid+256];
    __shared__ float red[256];
    red[tid] = v0 + v1; __syncthreads();
    for (int s = 128; s > 0; s >>= 1) { if (tid < s) red[tid] += red[tid+s]; __syncthreads(); }
    float mean = red[0]*(1.f/DD);
    __syncthreads();
    red[tid] = v0*v0 + v1*v1; __syncthreads();
    for (int s = 128; s > 0; s >>= 1) { if (tid < s) red[tid] += red[tid+s]; __syncthreads(); }
    float var = red[0]*(1.f/DD) - mean*mean;
    float rs = rsqrtf(var + 1e-5f);
    float o0 = (v0-mean)*rs*g[tid]     + b[tid];
    float o1 = (v1-mean)*rs*g[tid+256] + b[tid+256];
    out[row*DD + tid]     = o0;
    out[row*DD + tid+256] = o1;
    long ob = row*1536;
    bf16 hi, lo;
    split2(o0, hi, lo); As[ob+tid]     = hi; As[ob+512+tid]     = hi; As[ob+1024+tid]     = lo;
    split2(o1, hi, lo); As[ob+tid+256] = hi; As[ob+512+tid+256] = hi; As[ob+1024+tid+256] = lo;
}

__global__ void pe_kernel(float* __restrict__ pe)
{
    int idx = blockIdx.x*blockDim.x + threadIdx.x;
    if (idx >= SS_*DD) return;
    int d = idx & (DD-1);
    int s = idx >> 9;
    int i = d >> 1;
    double denom = exp(-log(10000.0) * (double)i / 256.0);
    double ang = (double)s * denom;
    pe[idx] = (d & 1) ? (float)cos(ang) : (float)sin(ang);
}

__global__ void add_pe2(const float* __restrict__ src, const float* __restrict__ pe,
                        float* __restrict__ out, bf16* __restrict__ As)
{
    int idx = blockIdx.x*blockDim.x + threadIdx.x;
    if (idx >= MS*DD) return;
    float v = src[idx] + pe[idx & (SS_*DD - 1)];
    out[idx] = v;
    int c = idx & 511;
    long row = idx >> 9;
    long ob = row*1536;
    bf16 hi, lo; split2(v, hi, lo);
    As[ob+c] = hi; As[ob+512+c] = hi; As[ob+1024+c] = lo;
}

// ---------------- host ----------------
static float *px, *py, *pqkv, *pa, *ppe;
static bf16  *pW, *pAx, *pAe, *pAff, *pAo, *pAq, *pBk, *pBv;

#define SM128 (3*(128*128 + 128*128) + 1024)
#define SM64  (4*(128*128 + 64*128) + 1024)
#define SMFLASH (49152 + 49152 + 32768 + 1024)

#define SZ_QKV (1536L*1536)
#define SZ_WO  (512L*1536)
#define SZ_W1  (2048L*1536)
#define SZ_W2  (512L*6144)
#define SZ_QW  (512L*1536)
#define SZ_KVW (1024L*1536)
#define L_ENC  (SZ_QKV + SZ_WO + SZ_W1 + SZ_W2)
#define L_DEC  (SZ_QKV + SZ_WO + SZ_QW + SZ_KVW + SZ_WO + SZ_W1 + SZ_W2)
#define DEC_BASE (6*L_ENC)

static void get_ptrs()
{
    if (px) return;
    cudaGetSymbolAddress((void**)&px,  g_x);
    cudaGetSymbolAddress((void**)&py,  g_y);
    cudaGetSymbolAddress((void**)&pqkv,g_qkv);
    cudaGetSymbolAddress((void**)&pa,  g_a);
    cudaGetSymbolAddress((void**)&ppe, g_pe);
    cudaGetSymbolAddress((void**)&pW,  g_W);
    cudaGetSymbolAddress((void**)&pAx, g_Ax);
    cudaGetSymbolAddress((void**)&pAe, g_Ae);
    cudaGetSymbolAddress((void**)&pAff,g_Aff);
    cudaGetSymbolAddress((void**)&pAo, g_Ao);
    cudaGetSymbolAddress((void**)&pAq, g_Aq);
    cudaGetSymbolAddress((void**)&pBk, g_Bk);
    cudaGetSymbolAddress((void**)&pBv, g_Bv);
    cudaFuncSetAttribute(gemm_mma<128,64,64,128,3>, cudaFuncAttributeMaxDynamicSharedMemorySize, SM128);
    cudaFuncSetAttribute(gemm_mma<64,64,32,128,4>,  cudaFuncAttributeMaxDynamicSharedMemorySize, SM64);
    cudaFuncSetAttribute(flash_attn, cudaFuncAttributeMaxDynamicSharedMemorySize, SMFLASH);
}

static void gemmN(const bf16* A, const bf16* B, float* C, const float* bias,
                  bf16* Cs, int nreg, int M, int N, int Kp, int ldc, int relu)
{
    if (N == 512 || N == 1536) {
        dim3 grid(N/64, M/128, 1);
        gemm_mma<64,64,32,128,4><<<grid,128,SM64>>>(A,B,C,bias,Cs,nreg,Kp,ldc,relu);
    } else {
        dim3 grid(N/128, M/128, 1);
        gemm_mma<128,64,64,128,3><<<grid,128,SM128>>>(A,B,C,bias,Cs,nreg,Kp,ldc,relu);
    }
}

static void attn_core(int qld, const float* kvsrc, int kvld,
                      const bf16* Wo, const float* bo, int causal)
{
    pack_att<<<10240,256>>>(pqkv, qld, kvsrc, kvld, pAq, pBk, pBv);
    flash_attn<<<dim3(4,64),256,SMFLASH>>>(pAq, pBk, pBv, pAo, causal);
    gemmN(pAo, Wo, pa, bo, nullptr, 0, MS, 512, 1536, 512, 0);
}

extern "C" void kernel_launch(void* const* d_in, const int* in_sizes, int n_in,
                              void* d_out, int out_size)
{
    const float* src  = (const float*)d_in[0];
    const float* tgt  = (const float*)d_in[1];
    const float* eaw  = (const float*)d_in[2];
    const float* eab  = (const float*)d_in[3];
    const float* ewo  = (const float*)d_in[4];
    const float* ebo  = (const float*)d_in[5];
    const float* elg  = (const float*)d_in[6];
    const float* elb  = (const float*)d_in[7];
    const float* efw1 = (const float*)d_in[8];
    const float* efb1 = (const float*)d_in[9];
    const float* efw2 = (const float*)d_in[10];
    const float* efb2 = (const float*)d_in[11];
    const float* daw  = (const float*)d_in[12];
    const float* dab  = (const float*)d_in[13];
    const float* dwo  = (const float*)d_in[14];
    const float* dbo  = (const float*)d_in[15];
    const float* dlg  = (const float*)d_in[16];
    const float* dlb  = (const float*)d_in[17];
    const float* dfw1 = (const float*)d_in[18];
    const float* dfb1 = (const float*)d_in[19];
    const float* dfw2 = (const float*)d_in[20];
    const float* dfb2 = (const float*)d_in[21];
    float* out = (float*)d_out;

    get_ptrs();

    const long WATT = (long)3*HH*DD*DKK;
    const long WO_S = (long)HD*DD;

    pack_BT<<<dim3(16,2,144),dim3(32,8)>>>(eaw, pW, 512, 64, 64,
                                           WATT, 512L*64, 24, L_ENC);
    pack_BT<<<dim3(16,16,6),dim3(32,8)>>>(ewo, pW + SZ_QKV, 512, 512, 512,
                                          WO_S, 0, 1, L_ENC);
    pack_BT<<<dim3(16,64,6),dim3(32,8)>>>(efw1, pW + SZ_QKV + SZ_WO, 512, 2048, 2048,
                                          (long)DD*DFFN, 0, 1, L_ENC);
    pack_BT<<<dim3(64,16,6),dim3(32,8)>>>(efw2, pW + SZ_QKV + SZ_WO + SZ_W1,
                                          2048, 512, 512, (long)DFFN*DD, 0, 1, L_ENC);

    bf16* db = pW + DEC_BASE;
    pack_BT<<<dim3(16,2,144),dim3(32,8)>>>(daw, db, 512, 64, 64,
                                           2*WATT, 512L*64, 24, L_DEC);
    pack_BT<<<dim3(16,16,6),dim3(32,8)>>>(dwo, db + SZ_QKV, 512, 512, 512,
                                          2*WO_S, 0, 1, L_DEC);
    pack_BT<<<dim3(16,2,48),dim3(32,8)>>>(daw + WATT, db + SZ_QKV + SZ_WO,
                                          512, 64, 64, 2*WATT, 512L*64, 8, L_DEC);
    pack_BT<<<dim3(16,2,96),dim3(32,8)>>>(daw + WATT + 8L*512*64,
                                          db + SZ_QKV + SZ_WO + SZ_QW,
                                          512, 64, 64, 2*WATT, 512L*64, 16, L_DEC);
    pack_BT<<<dim3(16,16,6),dim3(32,8)>>>(dwo + WO_S,
                                          db + SZ_QKV + SZ_WO + SZ_QW + SZ_KVW,
                                          512, 512, 512, 2*WO_S, 0, 1, L_DEC);
    pack_BT<<<dim3(16,64,6),dim3(32,8)>>>(dfw1, db + SZ_QKV + 2*SZ_WO + SZ_QW + SZ_KVW,
                                          512, 2048, 2048, (long)DD*DFFN, 0, 1, L_DEC);
    pack_BT<<<dim3(64,16,6),dim3(32,8)>>>(dfw2,
                                          db + SZ_QKV + 2*SZ_WO + SZ_QW + SZ_KVW + SZ_W1,
                                          2048, 512, 512, (long)DFFN*DD, 0, 1, L_DEC);

    pe_kernel<<<(SS_*DD+255)/256,256>>>(ppe);
    add_pe2<<<(MS*DD+255)/256,256>>>(src, ppe, px, pAx);

    for (int l = 0; l < LL; l++) {
        bf16* base = pW + (long)l*L_ENC;
        gemmN(pAx, base, pqkv, eab + (long)l*1536, nullptr, 0, MS, 1536, 1536, 1536, 0);
        attn_core(1536, pqkv + 512, 1536, base + SZ_QKV, ebo + (long)l*DD, 0);
        add_ln2<<<MS,256>>>(px, pa, elg + (long)l*2*DD, elb + (long)l*2*DD, px, pAx);
        gemmN(pAx, base + SZ_QKV + SZ_WO, nullptr, efb1 + (long)l*DFFN, pAff, 2048,
              MS, 2048, 1536, 2048, 1);
        gemmN(pAff, base + SZ_QKV + SZ_WO + SZ_W1, pa, efb2 + (long)l*DD, nullptr, 0,
              MS, 512, 6144, 512, 0);
        bf16* As2 = (l == LL-1) ? pAe : pAx;
        add_ln2<<<MS,256>>>(px, pa, elg + (long)l*2*DD + DD, elb + (long)l*2*DD + DD, px, As2);
    }

    add_pe2<<<(MS*DD+255)/256,256>>>(tgt, ppe, py, pAx);

    for (int l = 0; l < LL; l++) {
        bf16* base = pW + DEC_BASE + (long)l*L_DEC;
        gemmN(pAx, base, pqkv, dab + (long)(l*2)*1536, nullptr, 0, MS, 1536, 1536, 1536, 0);
        attn_core(1536, pqkv + 512, 1536, base + SZ_QKV, dbo + (long)(l*2)*DD, 1);
        add_ln2<<<MS,256>>>(py, pa, dlg + (long)l*3*DD, dlb + (long)l*3*DD, py, pAx);
        gemmN(pAx, base + SZ_QKV + SZ_WO, pqkv, dab + (long)(l*2+1)*1536, nullptr, 0,
              MS, 512, 1536, 512, 0);
        gemmN(pAe, base + SZ_QKV + SZ_WO + SZ_QW, pqkv + (long)MS*512,
              dab + (long)(l*2+1)*1536 + 512, nullptr, 0, MS, 1024, 1536, 1024, 0);
        attn_core(512, pqkv + (long)MS*512, 1024,
                  base + SZ_QKV + SZ_WO + SZ_QW + SZ_KVW, dbo + (long)(l*2+1)*DD, 0);
        add_ln2<<<MS,256>>>(py, pa, dlg + (long)l*3*DD + DD, dlb + (long)l*3*DD + DD, py, pAx);
        gemmN(pAx, base + SZ_QKV + 2*SZ_WO + SZ_QW + SZ_KVW, nullptr,
              dfb1 + (long)l*DFFN, pAff, 2048, MS, 2048, 1536, 2048, 1);
        gemmN(pAff, base + SZ_QKV + 2*SZ_WO + SZ_QW + SZ_KVW + SZ_W1, pa,
              dfb2 + (long)l*DD, nullptr, 0, MS, 512, 6144, 512, 0);
        float* yo = (l == LL-1) ? out : py;
        add_ln2<<<MS,256>>>(py, pa, dlg + (long)l*3*DD + 2*DD, dlb + (long)l*3*DD + 2*DD, yo, pAx);
    }
}

// round 16
// speedup vs baseline: 1.0068x; 1.0068x over previous
#include <cuda_runtime.h>
#include <cuda_bf16.h>
#include <math.h>
#include <stdint.h>

#define BB   8
#define SS_  512
#define LL   6
#define HH   8
#define DD   512
#define DKK  64
#define DFFN 2048
#define MS   (BB*SS_)
#define HD   (HH*DKK)

typedef __nv_bfloat16 bf16;

// ---------------- scratch ----------------
__device__ __align__(1024) bf16  g_W  [132120576];
__device__ __align__(1024) bf16  g_Ax [(long)MS*1536];
__device__ __align__(1024) bf16  g_Ae [(long)MS*1536];
__device__ __align__(1024) bf16  g_Aff[(long)MS*6144];
__device__ __align__(1024) bf16  g_Ao [(long)MS*1536];
__device__ __align__(1024) bf16  g_Aq [(long)64*512*192];
__device__ __align__(1024) bf16  g_Bk [(long)64*512*192];
__device__ __align__(1024) bf16  g_Bv [(long)64*64*1536];
__device__ __align__(1024) float g_qkv[(long)MS*1536];
__device__ __align__(1024) float g_x [MS*DD];
__device__ __align__(1024) float g_y [MS*DD];
__device__ __align__(1024) float g_a [MS*DD];
__device__ __align__(1024) float g_pe[SS_*DD];

// ---------------- helpers ----------------
__device__ __forceinline__ uint32_t smem_u32(const void* p) {
    uint32_t a;
    asm("{ .reg .u64 t; cvta.to.shared.u64 t, %1; cvt.u32.u64 %0, t; }" : "=r"(a) : "l"(p));
    return a;
}
#define SW128(o) ((o) ^ (((o) >> 3) & 0x70))

__device__ __forceinline__ void cp_async16(uint32_t daddr, const void* gptr) {
    asm volatile("cp.async.cg.shared.global [%0], [%1], 16;" :: "r"(daddr), "l"(gptr));
}
__device__ __forceinline__ void cp_commit() {
    asm volatile("cp.async.commit_group;" ::: "memory");
}
__device__ __forceinline__ void cp_wait(int w) {
    switch (w) {
    case 0: asm volatile("cp.async.wait_group 0;" ::: "memory"); break;
    case 1: asm volatile("cp.async.wait_group 1;" ::: "memory"); break;
    case 2: asm volatile("cp.async.wait_group 2;" ::: "memory"); break;
    default: asm volatile("cp.async.wait_group 3;" ::: "memory"); break;
    }
}
__device__ __forceinline__ void ldmx4(uint32_t* r, uint32_t addr) {
    asm volatile("ldmatrix.sync.aligned.m8n8.x4.shared.b16 {%0,%1,%2,%3}, [%4];"
                 : "=r"(r[0]), "=r"(r[1]), "=r"(r[2]), "=r"(r[3]) : "r"(addr));
}
__device__ __forceinline__ void mma16816(float* d, const uint32_t* a, const uint32_t* b) {
    asm volatile("mma.sync.aligned.m16n8k16.row.col.f32.bf16.bf16.f32 "
                 "{%0,%1,%2,%3}, {%4,%5,%6,%7}, {%8,%9}, {%0,%1,%2,%3};"
                 : "+f"(d[0]), "+f"(d[1]), "+f"(d[2]), "+f"(d[3])
                 : "r"(a[0]), "r"(a[1]), "r"(a[2]), "r"(a[3]), "r"(b[0]), "r"(b[1]));
}
__device__ __forceinline__ void split2(float v, bf16& hi, bf16& lo) {
    hi = __float2bfloat16(v);
    lo = __float2bfloat16(v - __bfloat162float(hi));
}
__device__ __forceinline__ uint32_t pack_hi2(float a, float b, float& ra, float& rb) {
    __nv_bfloat162 h;
    h.x = __float2bfloat16(a); h.y = __float2bfloat16(b);
    ra = a - __bfloat162float(h.x);
    rb = b - __bfloat162float(h.y);
    return *(uint32_t*)&h;
}
__device__ __forceinline__ uint32_t pack_bf2(float a, float b) {
    __nv_bfloat162 h;
    h.x = __float2bfloat16(a); h.y = __float2bfloat16(b);
    return *(uint32_t*)&h;
}

// ---------------- GEMM (4 warps; STAGES-deep cp.async pipeline) ----------------
template<int BN, int WM, int WN, int THREADS, int STAGES>
__global__ __launch_bounds__(THREADS, 2)
void gemm_mma(const bf16* __restrict__ A, const bf16* __restrict__ B,
              float* __restrict__ C, const float* __restrict__ bias,
              bf16* __restrict__ Cs, int nreg,
              int Kp, int ldc, int relu)
{
    constexpr int BM = 128;
    constexpr int ASZ = BM*128, BSZ = BN*128, STG = ASZ + BSZ;
    constexpr int MT = WM/16, NT = WN/8, WCOLS = BN/WN;
    const int ldcs = 3*nreg;

    extern __shared__ char smraw[];
    char* sm = (char*)(((uintptr_t)smraw + 1023) & ~(uintptr_t)1023);

    const int tid = threadIdx.x;
    const int wid = tid >> 5, lane = tid & 31;
    const int wm = (wid / WCOLS) * WM;
    const int wn = (wid % WCOLS) * WN;

    const long bm = (long)blockIdx.y * BM;
    const long bn = (long)blockIdx.x * BN;
    const bf16* Ag = A + bm*(long)Kp;
    const bf16* Bg = B + bn*(long)Kp;
    const int nc = Kp >> 6;

    float acc[MT][NT][4];
    #pragma unroll
    for (int i = 0; i < MT; i++)
        #pragma unroll
        for (int j = 0; j < NT; j++)
            #pragma unroll
            for (int q = 0; q < 4; q++) acc[i][j][q] = 0.f;

    auto issue = [&](int c) {
        char* sa = sm + (c % STAGES)*STG;
        char* sb = sa + ASZ;
        uint32_t sa32 = smem_u32(sa), sb32 = smem_u32(sb);
        #pragma unroll
        for (int p = 0; p < BM*8/THREADS; p++) {
            int idx = tid + p*THREADS;
            int row = idx >> 3, ch = idx & 7;
            cp_async16(sa32 + SW128((uint32_t)(row*128 + ch*16)),
                       Ag + (long)row*Kp + (long)c*64 + ch*8);
        }
        #pragma unroll
        for (int p = 0; p < BN*8/THREADS; p++) {
            int idx = tid + p*THREADS;
            int row = idx >> 3, ch = idx & 7;
            cp_async16(sb32 + SW128((uint32_t)(row*128 + ch*16)),
                       Bg + (long)row*Kp + (long)c*64 + ch*8);
        }
        cp_commit();
    };

    #pragma unroll
    for (int s = 0; s < STAGES; s++)
        if (s < nc) issue(s);

    for (int c = 0; c < nc; c++) {
        int rem = nc - 1 - c;
        cp_wait(rem < STAGES-1 ? rem : STAGES-1);
        __syncthreads();

        char* sa = sm + (c % STAGES)*STG;
        char* sb = sa + ASZ;
        uint32_t abase = smem_u32(sa), bbase = smem_u32(sb);

        #pragma unroll
        for (int ks = 0; ks < 4; ks++) {
            uint32_t af[MT][4], bfr[NT][2];
            #pragma unroll
            for (int i = 0; i < MT; i++) {
                uint32_t off = (uint32_t)((wm + i*16 + (lane & 15))*128 + ks*32 + (lane >> 4)*16);
                ldmx4(af[i], abase + SW128(off));
            }
            #pragma unroll
            for (int j = 0; j < NT/2; j++) {
                uint32_t off = (uint32_t)((wn + j*16 + (lane & 15))*128 + ks*32 + (lane >> 4)*16);
                uint32_t r[4];
                ldmx4(r, bbase + SW128(off));
                bfr[2*j][0]   = r[0]; bfr[2*j][1]   = r[2];
                bfr[2*j+1][0] = r[1]; bfr[2*j+1][1] = r[3];
            }
            #pragma unroll
            for (int i = 0; i < MT; i++)
                #pragma unroll
                for (int j = 0; j < NT; j++)
                    mma16816(acc[i][j], af[i], bfr[j]);
        }
        __syncthreads();
        if (c + STAGES < nc) issue(c + STAGES);
    }

    #pragma unroll
    for (int i = 0; i < MT; i++) {
        #pragma unroll
        for (int j = 0; j < NT; j++) {
            long r0  = bm + wm + i*16 + (lane >> 2);
            int  col = (int)bn + wn + j*8 + (lane & 3)*2;
            float2 v0 = make_float2(acc[i][j][0], acc[i][j][1]);
            float2 v1 = make_float2(acc[i][j][2], acc[i][j][3]);
            if (bias) {
                float2 bb = *(const float2*)(bias + col);
                v0.x += bb.x; v0.y += bb.y; v1.x += bb.x; v1.y += bb.y;
            }
            if (relu) {
                v0.x = fmaxf(v0.x, 0.f); v0.y = fmaxf(v0.y, 0.f);
                v1.x = fmaxf(v1.x, 0.f); v1.y = fmaxf(v1.y, 0.f);
            }
            if (C) {
                *(float2*)(C + r0*(long)ldc + col)     = v0;
                *(float2*)(C + (r0+8)*(long)ldc + col) = v1;
            }
            if (Cs) {
                bf16* p0 = Cs + r0*(long)ldcs + col;
                bf16* p1 = Cs + (r0+8)*(long)ldcs + col;
                __nv_bfloat162 h, l;
                h.x = __float2bfloat16(v0.x);
                h.y = __float2bfloat16(v0.y);
                l.x = __float2bfloat16(v0.x - __bfloat162float(h.x));
                l.y = __float2bfloat16(v0.y - __bfloat162float(h.y));
                *(__nv_bfloat162*)(p0)          = h;
                *(__nv_bfloat162*)(p0 + nreg)   = h;
                *(__nv_bfloat162*)(p0 + 2*nreg) = l;
                h.x = __float2bfloat16(v1.x);
                h.y = __float2bfloat16(v1.y);
                l.x = __float2bfloat16(v1.x - __bfloat162float(h.x));
                l.y = __float2bfloat16(v1.y - __bfloat162float(h.y));
                *(__nv_bfloat162*)(p1)          = h;
                *(__nv_bfloat162*)(p1 + nreg)   = h;
                *(__nv_bfloat162*)(p1 + 2*nreg) = l;
            }
        }
    }
}

// ---------------- fused flash attention (causal heavy-first) ----------------
__global__ __launch_bounds__(256, 1)
void flash_attn(const bf16* __restrict__ Aq, const bf16* __restrict__ Bk,
                const bf16* __restrict__ Bv, bf16* __restrict__ Ao, int causal)
{
    extern __shared__ char smraw[];
    uint32_t smQ = (smem_u32(smraw) + 1023) & ~1023u;
    uint32_t smK = smQ + 49152;
    uint32_t smV = smQ + 49152 + 49152;

    const int tid = threadIdx.x, wid = tid >> 5, lane = tid & 31;
    const int qt = causal ? (3 - blockIdx.x) : blockIdx.x;
    const int z = blockIdx.y;
    const int qbase = qt*128;
    const int nt = causal ? (2*qt + 2) : 8;

    {
        const bf16* qsrc = Aq + ((long)z*512 + qbase)*192;
        for (int i = tid; i < 3072; i += 256) {
            int ch = i >> 10, rem = i & 1023;
            int row = rem >> 3, seg = rem & 7;
            cp_async16(smQ + ch*16384 + SW128((uint32_t)(row*128 + seg*16)),
                       qsrc + (long)row*192 + ch*64 + seg*8);
        }
    }
    auto load_kv = [&](int t, int st) {
        uint32_t kst = smK + st*24576;
        uint32_t vst = smV + st*16384;
        const bf16* ksrc = Bk + ((long)z*512 + t*64)*192;
        for (int i = tid; i < 1536; i += 256) {
            int ch = i >> 9, rem = i & 511;
            int row = rem >> 3, seg = rem & 7;
            cp_async16(kst + ch*8192 + SW128((uint32_t)(row*128 + seg*16)),
                       ksrc + (long)row*192 + ch*64 + seg*8);
        }
        const bf16* vsrc = Bv + (long)z*64*1536;
        for (int i = tid; i < 1024; i += 256) {
            int hl = i >> 9, rem = i & 511;
            int dk = rem >> 3, seg = rem & 7;
            cp_async16(vst + hl*8192 + SW128((uint32_t)(dk*128 + seg*16)),
                       vsrc + (long)dk*1536 + hl*512 + t*64 + seg*8);
        }
    };

    load_kv(0, 0); cp_commit();
    if (nt > 1) { load_kv(1, 1); cp_commit(); }

    float m0 = -1e30f, m1 = -1e30f, l0 = 0.f, l1 = 0.f;
    float o[8][4];
    #pragma unroll
    for (int j = 0; j < 8; j++)
        #pragma unroll
        for (int q = 0; q < 4; q++) o[j][q] = 0.f;

    const int r0g = qbase + wid*16 + (lane >> 2);
    const int r1g = r0g + 8;

    for (int t = 0; t < nt; t++) {
        if (t + 1 < nt) asm volatile("cp.async.wait_group 1;" ::: "memory");
        else            asm volatile("cp.async.wait_group 0;" ::: "memory");
        __syncthreads();

        uint32_t kst = smK + (t & 1)*24576;
        uint32_t vst = smV + (t & 1)*16384;

        float sf[8][4];
        #pragma unroll
        for (int j = 0; j < 8; j++)
            #pragma unroll
            for (int q = 0; q < 4; q++) sf[j][q] = 0.f;

        #pragma unroll
        for (int kc = 0; kc < 12; kc++) {
            uint32_t af[4];
            ldmx4(af, smQ + (kc >> 2)*16384 +
                  SW128((uint32_t)((wid*16 + (lane & 15))*128 + (kc & 3)*32 + (lane >> 4)*16)));
            #pragma unroll
            for (int j = 0; j < 4; j++) {
                uint32_t r[4];
                ldmx4(r, kst + (kc >> 2)*8192 +
                      SW128((uint32_t)((j*16 + (lane & 15))*128 + (kc & 3)*32 + (lane >> 4)*16)));
                uint32_t b0[2] = {r[0], r[2]}, b1[2] = {r[1], r[3]};
                mma16816(sf[2*j],   af, b0);
                mma16816(sf[2*j+1], af, b1);
            }
        }

        if (causal) {
            #pragma unroll
            for (int j = 0; j < 8; j++) {
                int c0 = t*64 + j*8 + (lane & 3)*2;
                if (c0     > r0g) sf[j][0] = -1e30f;
                if (c0 + 1 > r0g) sf[j][1] = -1e30f;
                if (c0     > r1g) sf[j][2] = -1e30f;
                if (c0 + 1 > r1g) sf[j][3] = -1e30f;
            }
        }

        float tm0 = -1e30f, tm1 = -1e30f;
        #pragma unroll
        for (int j = 0; j < 8; j++) {
            tm0 = fmaxf(tm0, fmaxf(sf[j][0], sf[j][1]));
            tm1 = fmaxf(tm1, fmaxf(sf[j][2], sf[j][3]));
        }
        tm0 = fmaxf(tm0, __shfl_xor_sync(0xffffffffu, tm0, 1));
        tm0 = fmaxf(tm0, __shfl_xor_sync(0xffffffffu, tm0, 2));
        tm1 = fmaxf(tm1, __shfl_xor_sync(0xffffffffu, tm1, 1));
        tm1 = fmaxf(tm1, __shfl_xor_sync(0xffffffffu, tm1, 2));
        float mn0 = fmaxf(m0, tm0), mn1 = fmaxf(m1, tm1);
        float al0 = __expf(m0 - mn0), al1 = __expf(m1 - mn1);
        m0 = mn0; m1 = mn1;

        float rs0 = 0.f, rs1 = 0.f;
        #pragma unroll
        for (int j = 0; j < 8; j++) {
            float s0 = sf[j][0], s1 = sf[j][1], s2 = sf[j][2], s3 = sf[j][3];
            float p0 = (s0 > -1e29f) ? __expf(s0 - mn0) : 0.f;
            float p1 = (s1 > -1e29f) ? __expf(s1 - mn0) : 0.f;
            float p2 = (s2 > -1e29f) ? __expf(s2 - mn1) : 0.f;
            float p3 = (s3 > -1e29f) ? __expf(s3 - mn1) : 0.f;
            sf[j][0] = p0; sf[j][1] = p1; sf[j][2] = p2; sf[j][3] = p3;
            rs0 += p0 + p1; rs1 += p2 + p3;
        }
        rs0 += __shfl_xor_sync(0xffffffffu, rs0, 1);
        rs0 += __shfl_xor_sync(0xffffffffu, rs0, 2);
        rs1 += __shfl_xor_sync(0xffffffffu, rs1, 1);
        rs1 += __shfl_xor_sync(0xffffffffu, rs1, 2);
        l0 = l0*al0 + rs0;
        l1 = l1*al1 + rs1;
        #pragma unroll
        for (int j = 0; j < 8; j++) {
            o[j][0] *= al0; o[j][1] *= al0;
            o[j][2] *= al1; o[j][3] *= al1;
        }

        #pragma unroll
        for (int kc = 0; kc < 4; kc++) {
            float ra, rb;
            uint32_t ph[4], pl[4];
            ph[0] = pack_hi2(sf[2*kc][0],   sf[2*kc][1],   ra, rb); pl[0] = pack_bf2(ra, rb);
            ph[1] = pack_hi2(sf[2*kc][2],   sf[2*kc][3],   ra, rb); pl[1] = pack_bf2(ra, rb);
            ph[2] = pack_hi2(sf[2*kc+1][0], sf[2*kc+1][1], ra, rb); pl[2] = pack_bf2(ra, rb);
            ph[3] = pack_hi2(sf[2*kc+1][2], sf[2*kc+1][3], ra, rb); pl[3] = pack_bf2(ra, rb);
            #pragma unroll
            for (int j = 0; j < 4; j++) {
                uint32_t off = SW128((uint32_t)((j*16 + (lane & 15))*128 + kc*32 + (lane >> 4)*16));
                uint32_t rh[4], rl[4];
                ldmx4(rh, vst + off);
                ldmx4(rl, vst + 8192 + off);
                uint32_t bh0[2] = {rh[0], rh[2]}, bh1[2] = {rh[1], rh[3]};
                uint32_t bl0[2] = {rl[0], rl[2]}, bl1[2] = {rl[1], rl[3]};
                mma16816(o[2*j],   ph, bh0); mma16816(o[2*j+1], ph, bh1);
                mma16816(o[2*j],   ph, bl0); mma16816(o[2*j+1], ph, bl1);
                mma16816(o[2*j],   pl, bh0); mma16816(o[2*j+1], pl, bh1);
            }
        }

        __syncthreads();
        if (t + 2 < nt) { load_kv(t + 2, t & 1); cp_commit(); }
    }

    float i0 = 1.f / l0, i1 = 1.f / l1;
    long row0 = (long)(z >> 3)*512 + qbase + wid*16 + (lane >> 2);
    long row1 = row0 + 8;
    int colb = (z & 7)*64 + (lane & 3)*2;
    #pragma unroll
    for (int j = 0; j < 8; j++) {
        int c = colb + j*8;
        float v0 = o[j][0]*i0, v1 = o[j][1]*i0;
        float v2 = o[j][2]*i1, v3 = o[j][3]*i1;
        __nv_bfloat162 h, l;
        h.x = __float2bfloat16(v0); h.y = __float2bfloat16(v1);
        l.x = __float2bfloat16(v0 - __bfloat162float(h.x));
        l.y = __float2bfloat16(v1 - __bfloat162float(h.y));
        bf16* p0 = Ao + row0*1536 + c;
        *(__nv_bfloat162*)(p0)        = h;
        *(__nv_bfloat162*)(p0 + 512)  = h;
        *(__nv_bfloat162*)(p0 + 1024) = l;
        h.x = __float2bfloat16(v2); h.y = __float2bfloat16(v3);
        l.x = __float2bfloat16(v2 - __bfloat162float(h.x));
        l.y = __float2bfloat16(v3 - __bfloat162float(h.y));
        bf16* p1 = Ao + row1*1536 + c;
        *(__nv_bfloat162*)(p1)        = h;
        *(__nv_bfloat162*)(p1 + 512)  = h;
        *(__nv_bfloat162*)(p1 + 1024) = l;
    }
}

// ---------------- weight pack (layer-batched via ol) ----------------
__global__ void pack_BT(const float* __restrict__ src, bf16* __restrict__ out,
                        int rows, int cols, int ld, long s1, long s2, int zdiv, long ol)
{
    __shared__ float t[32][33];
    long z  = blockIdx.z;
    long zq = z / zdiv, zr = z % zdiv;
    const float* s = src + zq*s1 + zr*s2;
    bf16* o = out + zq*ol + zr*((long)cols*3L*rows);
    int k0 = blockIdx.x*32, n0 = blockIdx.y*32;
    int tx = threadIdx.x, ty = threadIdx.y;
    #pragma unroll
    for (int i = 0; i < 32; i += 8)
        t[ty+i][tx] = s[(long)(k0+ty+i)*ld + n0 + tx];
    __syncthreads();
    const long K3 = 3L*rows;
    #pragma unroll
    for (int i = 0; i < 32; i += 8) {
        float v = t[tx][ty+i];
        bf16 hi, lo; split2(v, hi, lo);
        long ob = (long)(n0 + ty + i)*K3 + k0 + tx;
        o[ob] = hi; o[ob + rows] = lo; o[ob + 2L*rows] = hi;
    }
}

// ---------------- merged attention operand pack ----------------
__global__ void pack_att(const float* __restrict__ qsrc, int qld,
                         const float* __restrict__ kvsrc, int kvld,
                         bf16* __restrict__ Aq, bf16* __restrict__ Bk,
                         bf16* __restrict__ Bv)
{
    __shared__ float t[32][33];
    int bid = blockIdx.x, tid = threadIdx.x;
    if (bid < 8192) {
        long idx = (long)bid*256 + tid;
        int kk = (int)(idx & 63);
        int s  = (int)((idx >> 6) & 511);
        int z  = (int)(idx >> 15);
        int b = z >> 3, h = z & 7;
        long srow = (long)(b*512 + s);
        float qv = qsrc[srow*qld + h*64 + kk] * 0.125f;
        float kv = kvsrc[srow*kvld + h*64 + kk];
        long ob = ((long)z*512 + s)*192;
        bf16 hi, lo;
        split2(qv, hi, lo); Aq[ob+kk] = hi; Aq[ob+64+kk] = hi; Aq[ob+128+kk] = lo;
        split2(kv, hi, lo); Bk[ob+kk] = hi; Bk[ob+64+kk] = lo; Bk[ob+128+kk] = hi;
    } else {
        int vb = bid - 8192;
        int gx = vb & 15, gy = (vb >> 4) & 1, z = vb >> 5;
        int k0 = gx*32, n0 = gy*32;
        int tx = tid & 31, ty = tid >> 5;
        const float* s = kvsrc + 512 + (long)(z >> 3)*(512L*kvld) + (z & 7)*64;
        #pragma unroll
        for (int i = 0; i < 32; i += 8)
            t[ty+i][tx] = s[(long)(k0+ty+i)*kvld + n0 + tx];
        __syncthreads();
        #pragma unroll
        for (int i = 0; i < 32; i += 8) {
            float v = t[tx][ty+i];
            bf16 hi, lo; split2(v, hi, lo);
            long ob = ((long)z*64 + n0 + ty + i)*1536 + k0 + tx;
            Bv[ob] = hi; Bv[ob + 512] = lo;
        }
    }
}

// ---------------- elementwise ----------------
__global__ void add_ln2(const float* __restrict__ x, const float* __restrict__ a,
                        const float* __restrict__ g, const float* __restrict__ b,
                        float* __restrict__ out, bf16* __restrict__ As)
{
    long row = blockIdx.x;
    int tid = threadIdx.x;
    const float* xr = x + row*DD;
    const float* ar = a + row*DD;
    float v0 = xr[tid]     + ar[tid];
    float v1 = xr[tid+256] + ar[tid+256];
    __shared__ float red[256];
    red[tid] = v0 + v1; __syncthreads();
    for (int s = 128; s > 0; s >>= 1) { if (tid < s) red[tid] += red[tid+s]; __syncthreads(); }
    float mean = red[0]*(1.f/DD);
    __syncthreads();
    red[tid] = v0*v0 + v1*v1; __syncthreads();
    for (int s = 128; s > 0; s >>= 1) { if (tid < s) red[tid] += red[tid+s]; __syncthreads(); }
    float var = red[0]*(1.f/DD) - mean*mean;
    float rs = rsqrtf(var + 1e-5f);
    float o0 = (v0-mean)*rs*g[tid]     + b[tid];
    float o1 = (v1-mean)*rs*g[tid+256] + b[tid+256];
    out[row*DD + tid]     = o0;
    out[row*DD + tid+256] = o1;
    long ob = row*1536;
    bf16 hi, lo;
    split2(o0, hi, lo); As[ob+tid]     = hi; As[ob+512+tid]     = hi; As[ob+1024+tid]     = lo;
    split2(o1, hi, lo); As[ob+tid+256] = hi; As[ob+512+tid+256] = hi; As[ob+1024+tid+256] = lo;
}

__global__ void pe_kernel(float* __restrict__ pe)
{
    int idx = blockIdx.x*blockDim.x + threadIdx.x;
    if (idx >= SS_*DD) return;
    int d = idx & (DD-1);
    int s = idx >> 9;
    int i = d >> 1;
    double denom = exp(-log(10000.0) * (double)i / 256.0);
    double ang = (double)s * denom;
    pe[idx] = (d & 1) ? (float)cos(ang) : (float)sin(ang);
}

__global__ void add_pe2(const float* __restrict__ src, const float* __restrict__ pe,
                        float* __restrict__ out, bf16* __restrict__ As)
{
    int idx = blockIdx.x*blockDim.x + threadIdx.x;
    if (idx >= MS*DD) return;
    float v = src[idx] + pe[idx & (SS_*DD - 1)];
    out[idx] = v;
    int c = idx & 511;
    long row = idx >> 9;
    long ob = row*1536;
    bf16 hi, lo; split2(v, hi, lo);
    As[ob+c] = hi; As[ob+512+c] = hi; As[ob+1024+c] = lo;
}

// ---------------- host ----------------
static float *px, *py, *pqkv, *pa, *ppe;
static bf16  *pW, *pAx, *pAe, *pAff, *pAo, *pAq, *pBk, *pBv;

#define SM128 (3*(128*128 + 128*128) + 1024)
#define SM64  (4*(128*128 + 64*128) + 1024)
#define SMFLASH (49152 + 49152 + 32768 + 1024)

#define SZ_QKV (1536L*1536)
#define SZ_WO  (512L*1536)
#define SZ_W1  (2048L*1536)
#define SZ_W2  (512L*6144)
#define SZ_QW  (512L*1536)
#define SZ_KVW (1024L*1536)
#define L_ENC  (SZ_QKV + SZ_WO + SZ_W1 + SZ_W2)
#define L_DEC  (SZ_QKV + SZ_WO + SZ_QW + SZ_KVW + SZ_WO + SZ_W1 + SZ_W2)
#define DEC_BASE (6*L_ENC)

static void get_ptrs()
{
    if (px) return;
    cudaGetSymbolAddress((void**)&px,  g_x);
    cudaGetSymbolAddress((void**)&py,  g_y);
    cudaGetSymbolAddress((void**)&pqkv,g_qkv);
    cudaGetSymbolAddress((void**)&pa,  g_a);
    cudaGetSymbolAddress((void**)&ppe, g_pe);
    cudaGetSymbolAddress((void**)&pW,  g_W);
    cudaGetSymbolAddress((void**)&pAx, g_Ax);
    cudaGetSymbolAddress((void**)&pAe, g_Ae);
    cudaGetSymbolAddress((void**)&pAff,g_Aff);
    cudaGetSymbolAddress((void**)&pAo, g_Ao);
    cudaGetSymbolAddress((void**)&pAq, g_Aq);
    cudaGetSymbolAddress((void**)&pBk, g_Bk);
    cudaGetSymbolAddress((void**)&pBv, g_Bv);
    cudaFuncSetAttribute(gemm_mma<128,64,64,128,3>, cudaFuncAttributeMaxDynamicSharedMemorySize, SM128);
    cudaFuncSetAttribute(gemm_mma<64,64,32,128,4>,  cudaFuncAttributeMaxDynamicSharedMemorySize, SM64);
    cudaFuncSetAttribute(flash_attn, cudaFuncAttributeMaxDynamicSharedMemorySize, SMFLASH);
}

static void gemmN(const bf16* A, const bf16* B, float* C, const float* bias,
                  bf16* Cs, int nreg, int M, int N, int Kp, int ldc, int relu)
{
    if (N == 512) {
        dim3 grid(N/64, M/128, 1);
        gemm_mma<64,64,32,128,4><<<grid,128,SM64>>>(A,B,C,bias,Cs,nreg,Kp,ldc,relu);
    } else {
        dim3 grid(N/128, M/128, 1);
        gemm_mma<128,64,64,128,3><<<grid,128,SM128>>>(A,B,C,bias,Cs,nreg,Kp,ldc,relu);
    }
}

static void attn_core(int qld, const float* kvsrc, int kvld,
                      const bf16* Wo, const float* bo, int causal)
{
    pack_att<<<10240,256>>>(pqkv, qld, kvsrc, kvld, pAq, pBk, pBv);
    flash_attn<<<dim3(4,64),256,SMFLASH>>>(pAq, pBk, pBv, pAo, causal);
    gemmN(pAo, Wo, pa, bo, nullptr, 0, MS, 512, 1536, 512, 0);
}

extern "C" void kernel_launch(void* const* d_in, const int* in_sizes, int n_in,
                              void* d_out, int out_size)
{
    const float* src  = (const float*)d_in[0];
    const float* tgt  = (const float*)d_in[1];
    const float* eaw  = (const float*)d_in[2];
    const float* eab  = (const float*)d_in[3];
    const float* ewo  = (const float*)d_in[4];
    const float* ebo  = (const float*)d_in[5];
    const float* elg  = (const float*)d_in[6];
    const float* elb  = (const float*)d_in[7];
    const float* efw1 = (const float*)d_in[8];
    const float* efb1 = (const float*)d_in[9];
    const float* efw2 = (const float*)d_in[10];
    const float* efb2 = (const float*)d_in[11];
    const float* daw  = (const float*)d_in[12];
    const float* dab  = (const float*)d_in[13];
    const float* dwo  = (const float*)d_in[14];
    const float* dbo  = (const float*)d_in[15];
    const float* dlg  = (const float*)d_in[16];
    const float* dlb  = (const float*)d_in[17];
    const float* dfw1 = (const float*)d_in[18];
    const float* dfb1 = (const float*)d_in[19];
    const float* dfw2 = (const float*)d_in[20];
    const float* dfb2 = (const float*)d_in[21];
    float* out = (float*)d_out;

    get_ptrs();

    const long WATT = (long)3*HH*DD*DKK;
    const long WO_S = (long)HD*DD;

    pack_BT<<<dim3(16,2,144),dim3(32,8)>>>(eaw, pW, 512, 64, 64,
                                           WATT, 512L*64, 24, L_ENC);
    pack_BT<<<dim3(16,16,6),dim3(32,8)>>>(ewo, pW + SZ_QKV, 512, 512, 512,
                                          WO_S, 0, 1, L_ENC);
    pack_BT<<<dim3(16,64,6),dim3(32,8)>>>(efw1, pW + SZ_QKV + SZ_WO, 512, 2048, 2048,
                                          (long)DD*DFFN, 0, 1, L_ENC);
    pack_BT<<<dim3(64,16,6),dim3(32,8)>>>(efw2, pW + SZ_QKV + SZ_WO + SZ_W1,
                                          2048, 512, 512, (long)DFFN*DD, 0, 1, L_ENC);

    bf16* db = pW + DEC_BASE;
    pack_BT<<<dim3(16,2,144),dim3(32,8)>>>(daw, db, 512, 64, 64,
                                           2*WATT, 512L*64, 24, L_DEC);
    pack_BT<<<dim3(16,16,6),dim3(32,8)>>>(dwo, db + SZ_QKV, 512, 512, 512,
                                          2*WO_S, 0, 1, L_DEC);
    pack_BT<<<dim3(16,2,48),dim3(32,8)>>>(daw + WATT, db + SZ_QKV + SZ_WO,
                                          512, 64, 64, 2*WATT, 512L*64, 8, L_DEC);
    pack_BT<<<dim3(16,2,96),dim3(32,8)>>>(daw + WATT + 8L*512*64,
                                          db + SZ_QKV + SZ_WO + SZ_QW,
                                          512, 64, 64, 2*WATT, 512L*64, 16, L_DEC);
    pack_BT<<<dim3(16,16,6),dim3(32,8)>>>(dwo + WO_S,
                                          db + SZ_QKV + SZ_WO + SZ_QW + SZ_KVW,
                                          512, 512, 512, 2*WO_S, 0, 1, L_DEC);
    pack_BT<<<dim3(16,64,6),dim3(32,8)>>>(dfw1, db + SZ_QKV + 2*SZ_WO + SZ_QW + SZ_KVW,
                                          512, 2048, 2048, (long)DD*DFFN, 0, 1, L_DEC);
    pack_BT<<<dim3(64,16,6),dim3(32,8)>>>(dfw2,
                                          db + SZ_QKV + 2*SZ_WO + SZ_QW + SZ_KVW + SZ_W1,
                                          2048, 512, 512, (long)DFFN*DD, 0, 1, L_DEC);

    pe_kernel<<<(SS_*DD+255)/256,256>>>(ppe);
    add_pe2<<<(MS*DD+255)/256,256>>>(src, ppe, px, pAx);

    for (int l = 0; l < LL; l++) {
        bf16* base = pW + (long)l*L_ENC;
        gemmN(pAx, base, pqkv, eab + (long)l*1536, nullptr, 0, MS, 1536, 1536, 1536, 0);
        attn_core(1536, pqkv + 512, 1536, base + SZ_QKV, ebo + (long)l*DD, 0);
        add_ln2<<<MS,256>>>(px, pa, elg + (long)l*2*DD, elb + (long)l*2*DD, px, pAx);
        gemmN(pAx, base + SZ_QKV + SZ_WO, nullptr, efb1 + (long)l*DFFN, pAff, 2048,
              MS, 2048, 1536, 2048, 1);
        gemmN(pAff, base + SZ_QKV + SZ_WO + SZ_W1, pa, efb2 + (long)l*DD, nullptr, 0,
              MS, 512, 6144, 512, 0);
        bf16* As2 = (l == LL-1) ? pAe : pAx;
        add_ln2<<<MS,256>>>(px, pa, elg + (long)l*2*DD + DD, elb + (long)l*2*DD + DD, px, As2);
    }

    add_pe2<<<(MS*DD+255)/256,256>>>(tgt, ppe, py, pAx);

    for (int l = 0; l < LL; l++) {
        bf16* base = pW + DEC_BASE + (long)l*L_DEC;
        gemmN(pAx, base, pqkv, dab + (long)(l*2)*1536, nullptr, 0, MS, 1536, 1536, 1536, 0);
        attn_core(1536, pqkv + 512, 1536, base + SZ_QKV, dbo + (long)(l*2)*DD, 1);
        add_ln2<<<MS,256>>>(py, pa, dlg + (long)l*3*DD, dlb + (long)l*3*DD, py, pAx);
        gemmN(pAx, base + SZ_QKV + SZ_WO, pqkv, dab + (long)(l*2+1)*1536, nullptr, 0,
              MS, 512, 1536, 512, 0);
        gemmN(pAe, base + SZ_QKV + SZ_WO + SZ_QW, pqkv + (long)MS*512,
              dab + (long)(l*2+1)*1536 + 512, nullptr, 0, MS, 1024, 1536, 1024, 0);
        attn_core(512, pqkv + (long)MS*512, 1024,
                  base + SZ_QKV + SZ_WO + SZ_QW + SZ_KVW, dbo + (long)(l*2+1)*DD, 0);
        add_ln2<<<MS,256>>>(py, pa, dlg + (long)l*3*DD + DD, dlb + (long)l*3*DD + DD, py, pAx);
        gemmN(pAx, base + SZ_QKV + 2*SZ_WO + SZ_QW + SZ_KVW, nullptr,
              dfb1 + (long)l*DFFN, pAff, 2048, MS, 2048, 1536, 2048, 1);
        gemmN(pAff, base + SZ_QKV + 2*SZ_WO + SZ_QW + SZ_KVW + SZ_W1, pa,
              dfb2 + (long)l*DD, nullptr, 0, MS, 512, 6144, 512, 0);
        float* yo = (l == LL-1) ? out : py;
        add_ln2<<<MS,256>>>(py, pa, dlg + (long)l*3*DD + 2*DD, dlb + (long)l*3*DD + 2*DD, yo, pAx);
    }
}

// round 17
// speedup vs baseline: 1.0116x; 1.0048x over previous
#include <cuda_runtime.h>
#include <cuda_bf16.h>
#include <math.h>
#include <stdint.h>

#define BB   8
#define SS_  512
#define LL   6
#define HH   8
#define DD   512
#define DKK  64
#define DFFN 2048
#define MS   (BB*SS_)
#define HD   (HH*DKK)

typedef __nv_bfloat16 bf16;

// ---------------- scratch ----------------
__device__ __align__(1024) bf16  g_W  [132120576];
__device__ __align__(1024) bf16  g_Ax [(long)MS*1536];
__device__ __align__(1024) bf16  g_Ae [(long)MS*1536];
__device__ __align__(1024) bf16  g_Aff[(long)MS*6144];
__device__ __align__(1024) bf16  g_Ao [(long)MS*1536];
__device__ __align__(1024) bf16  g_Aq [(long)64*512*192];
__device__ __align__(1024) bf16  g_Bk [(long)64*512*192];
__device__ __align__(1024) bf16  g_Bv [(long)64*64*1536];
__device__ __align__(1024) float g_qkv[(long)MS*1536];
__device__ __align__(1024) float g_x [MS*DD];
__device__ __align__(1024) float g_y [MS*DD];
__device__ __align__(1024) float g_a [MS*DD];
__device__ __align__(1024) float g_pe[SS_*DD];

// ---------------- helpers ----------------
__device__ __forceinline__ uint32_t smem_u32(const void* p) {
    uint32_t a;
    asm("{ .reg .u64 t; cvta.to.shared.u64 t, %1; cvt.u32.u64 %0, t; }" : "=r"(a) : "l"(p));
    return a;
}
#define SW128(o) ((o) ^ (((o) >> 3) & 0x70))

__device__ __forceinline__ void cp_async16(uint32_t daddr, const void* gptr) {
    asm volatile("cp.async.cg.shared.global [%0], [%1], 16;" :: "r"(daddr), "l"(gptr));
}
__device__ __forceinline__ void cp_commit() {
    asm volatile("cp.async.commit_group;" ::: "memory");
}
__device__ __forceinline__ void cp_wait(int w) {
    switch (w) {
    case 0: asm volatile("cp.async.wait_group 0;" ::: "memory"); break;
    case 1: asm volatile("cp.async.wait_group 1;" ::: "memory"); break;
    case 2: asm volatile("cp.async.wait_group 2;" ::: "memory"); break;
    default: asm volatile("cp.async.wait_group 3;" ::: "memory"); break;
    }
}
__device__ __forceinline__ void ldmx4(uint32_t* r, uint32_t addr) {
    asm volatile("ldmatrix.sync.aligned.m8n8.x4.shared.b16 {%0,%1,%2,%3}, [%4];"
                 : "=r"(r[0]), "=r"(r[1]), "=r"(r[2]), "=r"(r[3]) : "r"(addr));
}
__device__ __forceinline__ void mma16816(float* d, const uint32_t* a, const uint32_t* b) {
    asm volatile("mma.sync.aligned.m16n8k16.row.col.f32.bf16.bf16.f32 "
                 "{%0,%1,%2,%3}, {%4,%5,%6,%7}, {%8,%9}, {%0,%1,%2,%3};"
                 : "+f"(d[0]), "+f"(d[1]), "+f"(d[2]), "+f"(d[3])
                 : "r"(a[0]), "r"(a[1]), "r"(a[2]), "r"(a[3]), "r"(b[0]), "r"(b[1]));
}
__device__ __forceinline__ void split2(float v, bf16& hi, bf16& lo) {
    hi = __float2bfloat16(v);
    lo = __float2bfloat16(v - __bfloat162float(hi));
}
__device__ __forceinline__ uint32_t pack_hi2(float a, float b, float& ra, float& rb) {
    __nv_bfloat162 h;
    h.x = __float2bfloat16(a); h.y = __float2bfloat16(b);
    ra = a - __bfloat162float(h.x);
    rb = b - __bfloat162float(h.y);
    return *(uint32_t*)&h;
}
__device__ __forceinline__ uint32_t pack_bf2(float a, float b) {
    __nv_bfloat162 h;
    h.x = __float2bfloat16(a); h.y = __float2bfloat16(b);
    return *(uint32_t*)&h;
}
__device__ __forceinline__ void split_pair(float a, float b, __nv_bfloat162& h, __nv_bfloat162& l) {
    h.x = __float2bfloat16(a); h.y = __float2bfloat16(b);
    l.x = __float2bfloat16(a - __bfloat162float(h.x));
    l.y = __float2bfloat16(b - __bfloat162float(h.y));
}

// ---------------- GEMM (4 warps; STAGES-deep cp.async pipeline) ----------------
template<int BN, int WM, int WN, int THREADS, int STAGES>
__global__ __launch_bounds__(THREADS, 2)
void gemm_mma(const bf16* __restrict__ A, const bf16* __restrict__ B,
              float* __restrict__ C, const float* __restrict__ bias,
              bf16* __restrict__ Cs, int nreg,
              int Kp, int ldc, int relu)
{
    constexpr int BM = 128;
    constexpr int ASZ = BM*128, BSZ = BN*128, STG = ASZ + BSZ;
    constexpr int MT = WM/16, NT = WN/8, WCOLS = BN/WN;
    const int ldcs = 3*nreg;

    extern __shared__ char smraw[];
    char* sm = (char*)(((uintptr_t)smraw + 1023) & ~(uintptr_t)1023);

    const int tid = threadIdx.x;
    const int wid = tid >> 5, lane = tid & 31;
    const int wm = (wid / WCOLS) * WM;
    const int wn = (wid % WCOLS) * WN;

    const long bm = (long)blockIdx.y * BM;
    const long bn = (long)blockIdx.x * BN;
    const bf16* Ag = A + bm*(long)Kp;
    const bf16* Bg = B + bn*(long)Kp;
    const int nc = Kp >> 6;

    float acc[MT][NT][4];
    #pragma unroll
    for (int i = 0; i < MT; i++)
        #pragma unroll
        for (int j = 0; j < NT; j++)
            #pragma unroll
            for (int q = 0; q < 4; q++) acc[i][j][q] = 0.f;

    auto issue = [&](int c) {
        char* sa = sm + (c % STAGES)*STG;
        char* sb = sa + ASZ;
        uint32_t sa32 = smem_u32(sa), sb32 = smem_u32(sb);
        #pragma unroll
        for (int p = 0; p < BM*8/THREADS; p++) {
            int idx = tid + p*THREADS;
            int row = idx >> 3, ch = idx & 7;
            cp_async16(sa32 + SW128((uint32_t)(row*128 + ch*16)),
                       Ag + (long)row*Kp + (long)c*64 + ch*8);
        }
        #pragma unroll
        for (int p = 0; p < BN*8/THREADS; p++) {
            int idx = tid + p*THREADS;
            int row = idx >> 3, ch = idx & 7;
            cp_async16(sb32 + SW128((uint32_t)(row*128 + ch*16)),
                       Bg + (long)row*Kp + (long)c*64 + ch*8);
        }
        cp_commit();
    };

    #pragma unroll
    for (int s = 0; s < STAGES; s++)
        if (s < nc) issue(s);

    for (int c = 0; c < nc; c++) {
        int rem = nc - 1 - c;
        cp_wait(rem < STAGES-1 ? rem : STAGES-1);
        __syncthreads();

        char* sa = sm + (c % STAGES)*STG;
        char* sb = sa + ASZ;
        uint32_t abase = smem_u32(sa), bbase = smem_u32(sb);

        #pragma unroll
        for (int ks = 0; ks < 4; ks++) {
            uint32_t af[MT][4], bfr[NT][2];
            #pragma unroll
            for (int i = 0; i < MT; i++) {
                uint32_t off = (uint32_t)((wm + i*16 + (lane & 15))*128 + ks*32 + (lane >> 4)*16);
                ldmx4(af[i], abase + SW128(off));
            }
            #pragma unroll
            for (int j = 0; j < NT/2; j++) {
                uint32_t off = (uint32_t)((wn + j*16 + (lane & 15))*128 + ks*32 + (lane >> 4)*16);
                uint32_t r[4];
                ldmx4(r, bbase + SW128(off));
                bfr[2*j][0]   = r[0]; bfr[2*j][1]   = r[2];
                bfr[2*j+1][0] = r[1]; bfr[2*j+1][1] = r[3];
            }
            #pragma unroll
            for (int i = 0; i < MT; i++)
                #pragma unroll
                for (int j = 0; j < NT; j++)
                    mma16816(acc[i][j], af[i], bfr[j]);
        }
        __syncthreads();
        if (c + STAGES < nc) issue(c + STAGES);
    }

    #pragma unroll
    for (int i = 0; i < MT; i++) {
        #pragma unroll
        for (int j = 0; j < NT; j++) {
            long r0  = bm + wm + i*16 + (lane >> 2);
            int  col = (int)bn + wn + j*8 + (lane & 3)*2;
            float2 v0 = make_float2(acc[i][j][0], acc[i][j][1]);
            float2 v1 = make_float2(acc[i][j][2], acc[i][j][3]);
            if (bias) {
                float2 bb = *(const float2*)(bias + col);
                v0.x += bb.x; v0.y += bb.y; v1.x += bb.x; v1.y += bb.y;
            }
            if (relu) {
                v0.x = fmaxf(v0.x, 0.f); v0.y = fmaxf(v0.y, 0.f);
                v1.x = fmaxf(v1.x, 0.f); v1.y = fmaxf(v1.y, 0.f);
            }
            if (C) {
                *(float2*)(C + r0*(long)ldc + col)     = v0;
                *(float2*)(C + (r0+8)*(long)ldc + col) = v1;
            }
            if (Cs) {
                bf16* p0 = Cs + r0*(long)ldcs + col;
                bf16* p1 = Cs + (r0+8)*(long)ldcs + col;
                __nv_bfloat162 h, l;
                split_pair(v0.x, v0.y, h, l);
                *(__nv_bfloat162*)(p0)          = h;
                *(__nv_bfloat162*)(p0 + nreg)   = h;
                *(__nv_bfloat162*)(p0 + 2*nreg) = l;
                split_pair(v1.x, v1.y, h, l);
                *(__nv_bfloat162*)(p1)          = h;
                *(__nv_bfloat162*)(p1 + nreg)   = h;
                *(__nv_bfloat162*)(p1 + 2*nreg) = l;
            }
        }
    }
}

// ---------------- fused flash attention (causal heavy-first) ----------------
__global__ __launch_bounds__(256, 1)
void flash_attn(const bf16* __restrict__ Aq, const bf16* __restrict__ Bk,
                const bf16* __restrict__ Bv, bf16* __restrict__ Ao, int causal)
{
    extern __shared__ char smraw[];
    uint32_t smQ = (smem_u32(smraw) + 1023) & ~1023u;
    uint32_t smK = smQ + 49152;
    uint32_t smV = smQ + 49152 + 49152;

    const int tid = threadIdx.x, wid = tid >> 5, lane = tid & 31;
    const int qt = causal ? (3 - blockIdx.x) : blockIdx.x;
    const int z = blockIdx.y;
    const int qbase = qt*128;
    const int nt = causal ? (2*qt + 2) : 8;

    {
        const bf16* qsrc = Aq + ((long)z*512 + qbase)*192;
        for (int i = tid; i < 3072; i += 256) {
            int ch = i >> 10, rem = i & 1023;
            int row = rem >> 3, seg = rem & 7;
            cp_async16(smQ + ch*16384 + SW128((uint32_t)(row*128 + seg*16)),
                       qsrc + (long)row*192 + ch*64 + seg*8);
        }
    }
    auto load_kv = [&](int t, int st) {
        uint32_t kst = smK + st*24576;
        uint32_t vst = smV + st*16384;
        const bf16* ksrc = Bk + ((long)z*512 + t*64)*192;
        for (int i = tid; i < 1536; i += 256) {
            int ch = i >> 9, rem = i & 511;
            int row = rem >> 3, seg = rem & 7;
            cp_async16(kst + ch*8192 + SW128((uint32_t)(row*128 + seg*16)),
                       ksrc + (long)row*192 + ch*64 + seg*8);
        }
        const bf16* vsrc = Bv + (long)z*64*1536;
        for (int i = tid; i < 1024; i += 256) {
            int hl = i >> 9, rem = i & 511;
            int dk = rem >> 3, seg = rem & 7;
            cp_async16(vst + hl*8192 + SW128((uint32_t)(dk*128 + seg*16)),
                       vsrc + (long)dk*1536 + hl*512 + t*64 + seg*8);
        }
    };

    load_kv(0, 0); cp_commit();
    if (nt > 1) { load_kv(1, 1); cp_commit(); }

    float m0 = -1e30f, m1 = -1e30f, l0 = 0.f, l1 = 0.f;
    float o[8][4];
    #pragma unroll
    for (int j = 0; j < 8; j++)
        #pragma unroll
        for (int q = 0; q < 4; q++) o[j][q] = 0.f;

    const int r0g = qbase + wid*16 + (lane >> 2);
    const int r1g = r0g + 8;

    for (int t = 0; t < nt; t++) {
        if (t + 1 < nt) asm volatile("cp.async.wait_group 1;" ::: "memory");
        else            asm volatile("cp.async.wait_group 0;" ::: "memory");
        __syncthreads();

        uint32_t kst = smK + (t & 1)*24576;
        uint32_t vst = smV + (t & 1)*16384;

        float sf[8][4];
        #pragma unroll
        for (int j = 0; j < 8; j++)
            #pragma unroll
            for (int q = 0; q < 4; q++) sf[j][q] = 0.f;

        #pragma unroll
        for (int kc = 0; kc < 12; kc++) {
            uint32_t af[4];
            ldmx4(af, smQ + (kc >> 2)*16384 +
                  SW128((uint32_t)((wid*16 + (lane & 15))*128 + (kc & 3)*32 + (lane >> 4)*16)));
            #pragma unroll
            for (int j = 0; j < 4; j++) {
                uint32_t r[4];
                ldmx4(r, kst + (kc >> 2)*8192 +
                      SW128((uint32_t)((j*16 + (lane & 15))*128 + (kc & 3)*32 + (lane >> 4)*16)));
                uint32_t b0[2] = {r[0], r[2]}, b1[2] = {r[1], r[3]};
                mma16816(sf[2*j],   af, b0);
                mma16816(sf[2*j+1], af, b1);
            }
        }

        if (causal) {
            #pragma unroll
            for (int j = 0; j < 8; j++) {
                int c0 = t*64 + j*8 + (lane & 3)*2;
                if (c0     > r0g) sf[j][0] = -1e30f;
                if (c0 + 1 > r0g) sf[j][1] = -1e30f;
                if (c0     > r1g) sf[j][2] = -1e30f;
                if (c0 + 1 > r1g) sf[j][3] = -1e30f;
            }
        }

        float tm0 = -1e30f, tm1 = -1e30f;
        #pragma unroll
        for (int j = 0; j < 8; j++) {
            tm0 = fmaxf(tm0, fmaxf(sf[j][0], sf[j][1]));
            tm1 = fmaxf(tm1, fmaxf(sf[j][2], sf[j][3]));
        }
        tm0 = fmaxf(tm0, __shfl_xor_sync(0xffffffffu, tm0, 1));
        tm0 = fmaxf(tm0, __shfl_xor_sync(0xffffffffu, tm0, 2));
        tm1 = fmaxf(tm1, __shfl_xor_sync(0xffffffffu, tm1, 1));
        tm1 = fmaxf(tm1, __shfl_xor_sync(0xffffffffu, tm1, 2));
        float mn0 = fmaxf(m0, tm0), mn1 = fmaxf(m1, tm1);
        float al0 = __expf(m0 - mn0), al1 = __expf(m1 - mn1);
        m0 = mn0; m1 = mn1;

        float rs0 = 0.f, rs1 = 0.f;
        #pragma unroll
        for (int j = 0; j < 8; j++) {
            float s0 = sf[j][0], s1 = sf[j][1], s2 = sf[j][2], s3 = sf[j][3];
            float p0 = (s0 > -1e29f) ? __expf(s0 - mn0) : 0.f;
            float p1 = (s1 > -1e29f) ? __expf(s1 - mn0) : 0.f;
            float p2 = (s2 > -1e29f) ? __expf(s2 - mn1) : 0.f;
            float p3 = (s3 > -1e29f) ? __expf(s3 - mn1) : 0.f;
            sf[j][0] = p0; sf[j][1] = p1; sf[j][2] = p2; sf[j][3] = p3;
            rs0 += p0 + p1; rs1 += p2 + p3;
        }
        rs0 += __shfl_xor_sync(0xffffffffu, rs0, 1);
        rs0 += __shfl_xor_sync(0xffffffffu, rs0, 2);
        rs1 += __shfl_xor_sync(0xffffffffu, rs1, 1);
        rs1 += __shfl_xor_sync(0xffffffffu, rs1, 2);
        l0 = l0*al0 + rs0;
        l1 = l1*al1 + rs1;
        #pragma unroll
        for (int j = 0; j < 8; j++) {
            o[j][0] *= al0; o[j][1] *= al0;
            o[j][2] *= al1; o[j][3] *= al1;
        }

        #pragma unroll
        for (int kc = 0; kc < 4; kc++) {
            float ra, rb;
            uint32_t ph[4], pl[4];
            ph[0] = pack_hi2(sf[2*kc][0],   sf[2*kc][1],   ra, rb); pl[0] = pack_bf2(ra, rb);
            ph[1] = pack_hi2(sf[2*kc][2],   sf[2*kc][3],   ra, rb); pl[1] = pack_bf2(ra, rb);
            ph[2] = pack_hi2(sf[2*kc+1][0], sf[2*kc+1][1], ra, rb); pl[2] = pack_bf2(ra, rb);
            ph[3] = pack_hi2(sf[2*kc+1][2], sf[2*kc+1][3], ra, rb); pl[3] = pack_bf2(ra, rb);
            #pragma unroll
            for (int j = 0; j < 4; j++) {
                uint32_t off = SW128((uint32_t)((j*16 + (lane & 15))*128 + kc*32 + (lane >> 4)*16));
                uint32_t rh[4], rl[4];
                ldmx4(rh, vst + off);
                ldmx4(rl, vst + 8192 + off);
                uint32_t bh0[2] = {rh[0], rh[2]}, bh1[2] = {rh[1], rh[3]};
                uint32_t bl0[2] = {rl[0], rl[2]}, bl1[2] = {rl[1], rl[3]};
                mma16816(o[2*j],   ph, bh0); mma16816(o[2*j+1], ph, bh1);
                mma16816(o[2*j],   ph, bl0); mma16816(o[2*j+1], ph, bl1);
                mma16816(o[2*j],   pl, bh0); mma16816(o[2*j+1], pl, bh1);
            }
        }

        __syncthreads();
        if (t + 2 < nt) { load_kv(t + 2, t & 1); cp_commit(); }
    }

    float i0 = 1.f / l0, i1 = 1.f / l1;
    long row0 = (long)(z >> 3)*512 + qbase + wid*16 + (lane >> 2);
    long row1 = row0 + 8;
    int colb = (z & 7)*64 + (lane & 3)*2;
    #pragma unroll
    for (int j = 0; j < 8; j++) {
        int c = colb + j*8;
        __nv_bfloat162 h, l;
        split_pair(o[j][0]*i0, o[j][1]*i0, h, l);
        bf16* p0 = Ao + row0*1536 + c;
        *(__nv_bfloat162*)(p0)        = h;
        *(__nv_bfloat162*)(p0 + 512)  = h;
        *(__nv_bfloat162*)(p0 + 1024) = l;
        split_pair(o[j][2]*i1, o[j][3]*i1, h, l);
        bf16* p1 = Ao + row1*1536 + c;
        *(__nv_bfloat162*)(p1)        = h;
        *(__nv_bfloat162*)(p1 + 512)  = h;
        *(__nv_bfloat162*)(p1 + 1024) = l;
    }
}

// ---------------- weight pack (layer-batched via ol) ----------------
__global__ void pack_BT(const float* __restrict__ src, bf16* __restrict__ out,
                        int rows, int cols, int ld, long s1, long s2, int zdiv, long ol)
{
    __shared__ float t[32][33];
    long z  = blockIdx.z;
    long zq = z / zdiv, zr = z % zdiv;
    const float* s = src + zq*s1 + zr*s2;
    bf16* o = out + zq*ol + zr*((long)cols*3L*rows);
    int k0 = blockIdx.x*32, n0 = blockIdx.y*32;
    int tx = threadIdx.x, ty = threadIdx.y;
    #pragma unroll
    for (int i = 0; i < 32; i += 8)
        t[ty+i][tx] = s[(long)(k0+ty+i)*ld + n0 + tx];
    __syncthreads();
    const long K3 = 3L*rows;
    #pragma unroll
    for (int i = 0; i < 32; i += 8) {
        float v = t[tx][ty+i];
        bf16 hi, lo; split2(v, hi, lo);
        long ob = (long)(n0 + ty + i)*K3 + k0 + tx;
        o[ob] = hi; o[ob + rows] = lo; o[ob + 2L*rows] = hi;
    }
}

// ---------------- merged attention operand pack (Q/K 2-wide vectorized) ----------------
__global__ void pack_att(const float* __restrict__ qsrc, int qld,
                         const float* __restrict__ kvsrc, int kvld,
                         bf16* __restrict__ Aq, bf16* __restrict__ Bk,
                         bf16* __restrict__ Bv)
{
    __shared__ float t[32][33];
    int bid = blockIdx.x, tid = threadIdx.x;
    if (bid < 4096) {
        long idx = (long)bid*256 + tid;          // 1M threads; 2 elems each
        int kk = (int)(idx & 31) * 2;
        int s  = (int)((idx >> 5) & 511);
        int z  = (int)(idx >> 14);
        int b = z >> 3, h = z & 7;
        long srow = (long)(b*512 + s);
        float2 qv = *(const float2*)(qsrc + srow*qld + h*64 + kk);
        float2 kv = *(const float2*)(kvsrc + srow*kvld + h*64 + kk);
        long ob = ((long)z*512 + s)*192;
        __nv_bfloat162 h2, l2;
        split_pair(qv.x*0.125f, qv.y*0.125f, h2, l2);
        *(__nv_bfloat162*)(Aq + ob + kk)       = h2;
        *(__nv_bfloat162*)(Aq + ob + 64 + kk)  = h2;
        *(__nv_bfloat162*)(Aq + ob + 128 + kk) = l2;
        split_pair(kv.x, kv.y, h2, l2);
        *(__nv_bfloat162*)(Bk + ob + kk)       = h2;
        *(__nv_bfloat162*)(Bk + ob + 64 + kk)  = l2;
        *(__nv_bfloat162*)(Bk + ob + 128 + kk) = h2;
    } else {
        int vb = bid - 4096;
        int gx = vb & 15, gy = (vb >> 4) & 1, z = vb >> 5;
        int k0 = gx*32, n0 = gy*32;
        int tx = tid & 31, ty = tid >> 5;
        const float* s = kvsrc + 512 + (long)(z >> 3)*(512L*kvld) + (z & 7)*64;
        #pragma unroll
        for (int i = 0; i < 32; i += 8)
            t[ty+i][tx] = s[(long)(k0+ty+i)*kvld + n0 + tx];
        __syncthreads();
        #pragma unroll
        for (int i = 0; i < 32; i += 8) {
            float v = t[tx][ty+i];
            bf16 hi, lo; split2(v, hi, lo);
            long ob = ((long)z*64 + n0 + ty + i)*1536 + k0 + tx;
            Bv[ob] = hi; Bv[ob + 512] = lo;
        }
    }
}

// ---------------- elementwise ----------------
__global__ void add_ln2(const float* __restrict__ x, const float* __restrict__ a,
                        const float* __restrict__ g, const float* __restrict__ b,
                        float* __restrict__ out, bf16* __restrict__ As)
{
    long row = blockIdx.x;
    int tid = threadIdx.x;
    const float* xr = x + row*DD;
    const float* ar = a + row*DD;
    float v0 = xr[tid]     + ar[tid];
    float v1 = xr[tid+256] + ar[tid+256];
    __shared__ float red[256];
    red[tid] = v0 + v1; __syncthreads();
    for (int s = 128; s > 0; s >>= 1) { if (tid < s) red[tid] += red[tid+s]; __syncthreads(); }
    float mean = red[0]*(1.f/DD);
    __syncthreads();
    red[tid] = v0*v0 + v1*v1; __syncthreads();
    for (int s = 128; s > 0; s >>= 1) { if (tid < s) red[tid] += red[tid+s]; __syncthreads(); }
    float var = red[0]*(1.f/DD) - mean*mean;
    float rs = rsqrtf(var + 1e-5f);
    float o0 = (v0-mean)*rs*g[tid]     + b[tid];
    float o1 = (v1-mean)*rs*g[tid+256] + b[tid+256];
    out[row*DD + tid]     = o0;
    out[row*DD + tid+256] = o1;
    long ob = row*1536;
    bf16 hi, lo;
    split2(o0, hi, lo); As[ob+tid]     = hi; As[ob+512+tid]     = hi; As[ob+1024+tid]     = lo;
    split2(o1, hi, lo); As[ob+tid+256] = hi; As[ob+512+tid+256] = hi; As[ob+1024+tid+256] = lo;
}

__global__ void pe_kernel(float* __restrict__ pe)
{
    int idx = blockIdx.x*blockDim.x + threadIdx.x;
    if (idx >= SS_*DD) return;
    int d = idx & (DD-1);
    int s = idx >> 9;
    int i = d >> 1;
    double denom = exp(-log(10000.0) * (double)i / 256.0);
    double ang = (double)s * denom;
    pe[idx] = (d & 1) ? (float)cos(ang) : (float)sin(ang);
}

__global__ void add_pe2(const float* __restrict__ src, const float* __restrict__ pe,
                        float* __restrict__ out, bf16* __restrict__ As)
{
    int idx = blockIdx.x*blockDim.x + threadIdx.x;
    if (idx >= MS*DD) return;
    float v = src[idx] + pe[idx & (SS_*DD - 1)];
    out[idx] = v;
    int c = idx & 511;
    long row = idx >> 9;
    long ob = row*1536;
    bf16 hi, lo; split2(v, hi, lo);
    As[ob+c] = hi; As[ob+512+c] = hi; As[ob+1024+c] = lo;
}

// ---------------- host ----------------
static float *px, *py, *pqkv, *pa, *ppe;
static bf16  *pW, *pAx, *pAe, *pAff, *pAo, *pAq, *pBk, *pBv;

#define SM128 (3*(128*128 + 128*128) + 1024)
#define SM64  (4*(128*128 + 64*128) + 1024)
#define SMFLASH (49152 + 49152 + 32768 + 1024)

#define SZ_QKV (1536L*1536)
#define SZ_WO  (512L*1536)
#define SZ_W1  (2048L*1536)
#define SZ_W2  (512L*6144)
#define SZ_QW  (512L*1536)
#define SZ_KVW (1024L*1536)
#define L_ENC  (SZ_QKV + SZ_WO + SZ_W1 + SZ_W2)
#define L_DEC  (SZ_QKV + SZ_WO + SZ_QW + SZ_KVW + SZ_WO + SZ_W1 + SZ_W2)
#define DEC_BASE (6*L_ENC)

static void get_ptrs()
{
    if (px) return;
    cudaGetSymbolAddress((void**)&px,  g_x);
    cudaGetSymbolAddress((void**)&py,  g_y);
    cudaGetSymbolAddress((void**)&pqkv,g_qkv);
    cudaGetSymbolAddress((void**)&pa,  g_a);
    cudaGetSymbolAddress((void**)&ppe, g_pe);
    cudaGetSymbolAddress((void**)&pW,  g_W);
    cudaGetSymbolAddress((void**)&pAx, g_Ax);
    cudaGetSymbolAddress((void**)&pAe, g_Ae);
    cudaGetSymbolAddress((void**)&pAff,g_Aff);
    cudaGetSymbolAddress((void**)&pAo, g_Ao);
    cudaGetSymbolAddress((void**)&pAq, g_Aq);
    cudaGetSymbolAddress((void**)&pBk, g_Bk);
    cudaGetSymbolAddress((void**)&pBv, g_Bv);
    cudaFuncSetAttribute(gemm_mma<128,64,64,128,3>, cudaFuncAttributeMaxDynamicSharedMemorySize, SM128);
    cudaFuncSetAttribute(gemm_mma<64,64,32,128,4>,  cudaFuncAttributeMaxDynamicSharedMemorySize, SM64);
    cudaFuncSetAttribute(flash_attn, cudaFuncAttributeMaxDynamicSharedMemorySize, SMFLASH);
}

static void gemmN(const bf16* A, const bf16* B, float* C, const float* bias,
                  bf16* Cs, int nreg, int M, int N, int Kp, int ldc, int relu)
{
    if (N == 512) {
        dim3 grid(N/64, M/128, 1);
        gemm_mma<64,64,32,128,4><<<grid,128,SM64>>>(A,B,C,bias,Cs,nreg,Kp,ldc,relu);
    } else {
        dim3 grid(N/128, M/128, 1);
        gemm_mma<128,64,64,128,3><<<grid,128,SM128>>>(A,B,C,bias,Cs,nreg,Kp,ldc,relu);
    }
}

static void attn_core(int qld, const float* kvsrc, int kvld,
                      const bf16* Wo, const float* bo, int causal)
{
    pack_att<<<6144,256>>>(pqkv, qld, kvsrc, kvld, pAq, pBk, pBv);
    flash_attn<<<dim3(4,64),256,SMFLASH>>>(pAq, pBk, pBv, pAo, causal);
    gemmN(pAo, Wo, pa, bo, nullptr, 0, MS, 512, 1536, 512, 0);
}

extern "C" void kernel_launch(void* const* d_in, const int* in_sizes, int n_in,
                              void* d_out, int out_size)
{
    const float* src  = (const float*)d_in[0];
    const float* tgt  = (const float*)d_in[1];
    const float* eaw  = (const float*)d_in[2];
    const float* eab  = (const float*)d_in[3];
    const float* ewo  = (const float*)d_in[4];
    const float* ebo  = (const float*)d_in[5];
    const float* elg  = (const float*)d_in[6];
    const float* elb  = (const float*)d_in[7];
    const float* efw1 = (const float*)d_in[8];
    const float* efb1 = (const float*)d_in[9];
    const float* efw2 = (const float*)d_in[10];
    const float* efb2 = (const float*)d_in[11];
    const float* daw  = (const float*)d_in[12];
    const float* dab  = (const float*)d_in[13];
    const float* dwo  = (const float*)d_in[14];
    const float* dbo  = (const float*)d_in[15];
    const float* dlg  = (const float*)d_in[16];
    const float* dlb  = (const float*)d_in[17];
    const float* dfw1 = (const float*)d_in[18];
    const float* dfb1 = (const float*)d_in[19];
    const float* dfw2 = (const float*)d_in[20];
    const float* dfb2 = (const float*)d_in[21];
    float* out = (float*)d_out;

    get_ptrs();

    const long WATT = (long)3*HH*DD*DKK;
    const long WO_S = (long)HD*DD;

    pack_BT<<<dim3(16,2,144),dim3(32,8)>>>(eaw, pW, 512, 64, 64,
                                           WATT, 512L*64, 24, L_ENC);
    pack_BT<<<dim3(16,16,6),dim3(32,8)>>>(ewo, pW + SZ_QKV, 512, 512, 512,
                                          WO_S, 0, 1, L_ENC);
    pack_BT<<<dim3(16,64,6),dim3(32,8)>>>(efw1, pW + SZ_QKV + SZ_WO, 512, 2048, 2048,
                                          (long)DD*DFFN, 0, 1, L_ENC);
    pack_BT<<<dim3(64,16,6),dim3(32,8)>>>(efw2, pW + SZ_QKV + SZ_WO + SZ_W1,
                                          2048, 512, 512, (long)DFFN*DD, 0, 1, L_ENC);

    bf16* db = pW + DEC_BASE;
    pack_BT<<<dim3(16,2,144),dim3(32,8)>>>(daw, db, 512, 64, 64,
                                           2*WATT, 512L*64, 24, L_DEC);
    pack_BT<<<dim3(16,16,6),dim3(32,8)>>>(dwo, db + SZ_QKV, 512, 512, 512,
                                          2*WO_S, 0, 1, L_DEC);
    pack_BT<<<dim3(16,2,48),dim3(32,8)>>>(daw + WATT, db + SZ_QKV + SZ_WO,
                                          512, 64, 64, 2*WATT, 512L*64, 8, L_DEC);
    pack_BT<<<dim3(16,2,96),dim3(32,8)>>>(daw + WATT + 8L*512*64,
                                          db + SZ_QKV + SZ_WO + SZ_QW,
                                          512, 64, 64, 2*WATT, 512L*64, 16, L_DEC);
    pack_BT<<<dim3(16,16,6),dim3(32,8)>>>(dwo + WO_S,
                                          db + SZ_QKV + SZ_WO + SZ_QW + SZ_KVW,
                                          512, 512, 512, 2*WO_S, 0, 1, L_DEC);
    pack_BT<<<dim3(16,64,6),dim3(32,8)>>>(dfw1, db + SZ_QKV + 2*SZ_WO + SZ_QW + SZ_KVW,
                                          512, 2048, 2048, (long)DD*DFFN, 0, 1, L_DEC);
    pack_BT<<<dim3(64,16,6),dim3(32,8)>>>(dfw2,
                                          db + SZ_QKV + 2*SZ_WO + SZ_QW + SZ_KVW + SZ_W1,
                                          2048, 512, 512, (long)DFFN*DD, 0, 1, L_DEC);

    pe_kernel<<<(SS_*DD+255)/256,256>>>(ppe);
    add_pe2<<<(MS*DD+255)/256,256>>>(src, ppe, px, pAx);

    for (int l = 0; l < LL; l++) {
        bf16* base = pW + (long)l*L_ENC;
        gemmN(pAx, base, pqkv, eab + (long)l*1536, nullptr, 0, MS, 1536, 1536, 1536, 0);
        attn_core(1536, pqkv + 512, 1536, base + SZ_QKV, ebo + (long)l*DD, 0);
        add_ln2<<<MS,256>>>(px, pa, elg + (long)l*2*DD, elb + (long)l*2*DD, px, pAx);
        gemmN(pAx, base + SZ_QKV + SZ_WO, nullptr, efb1 + (long)l*DFFN, pAff, 2048,
              MS, 2048, 1536, 2048, 1);
        gemmN(pAff, base + SZ_QKV + SZ_WO + SZ_W1, pa, efb2 + (long)l*DD, nullptr, 0,
              MS, 512, 6144, 512, 0);
        bf16* As2 = (l == LL-1) ? pAe : pAx;
        add_ln2<<<MS,256>>>(px, pa, elg + (long)l*2*DD + DD, elb + (long)l*2*DD + DD, px, As2);
    }

    add_pe2<<<(MS*DD+255)/256,256>>>(tgt, ppe, py, pAx);

    for (int l = 0; l < LL; l++) {
        bf16* base = pW + DEC_BASE + (long)l*L_DEC;
        gemmN(pAx, base, pqkv, dab + (long)(l*2)*1536, nullptr, 0, MS, 1536, 1536, 1536, 0);
        attn_core(1536, pqkv + 512, 1536, base + SZ_QKV, dbo + (long)(l*2)*DD, 1);
        add_ln2<<<MS,256>>>(py, pa, dlg + (long)l*3*DD, dlb + (long)l*3*DD, py, pAx);
        gemmN(pAx, base + SZ_QKV + SZ_WO, pqkv, dab + (long)(l*2+1)*1536, nullptr, 0,
              MS, 512, 1536, 512, 0);
        gemmN(pAe, base + SZ_QKV + SZ_WO + SZ_QW, pqkv + (long)MS*512,
              dab + (long)(l*2+1)*1536 + 512, nullptr, 0, MS, 1024, 1536, 1024, 0);
        attn_core(512, pqkv + (long)MS*512, 1024,
                  base + SZ_QKV + SZ_WO + SZ_QW + SZ_KVW, dbo + (long)(l*2+1)*DD, 0);
        add_ln2<<<MS,256>>>(py, pa, dlg + (long)l*3*DD + DD, dlb + (long)l*3*DD + DD, py, pAx);
        gemmN(pAx, base + SZ_QKV + 2*SZ_WO + SZ_QW + SZ_KVW, nullptr,
              dfb1 + (long)l*DFFN, pAff, 2048, MS, 2048, 1536, 2048, 1);
        gemmN(pAff, base + SZ_QKV + 2*SZ_WO + SZ_QW + SZ_KVW + SZ_W1, pa,
              dfb2 + (long)l*DD, nullptr, 0, MS, 512, 6144, 512, 0);
        float* yo = (l == LL-1) ? out : py;
        add_ln2<<<MS,256>>>(py, pa, dlg + (long)l*3*DD + 2*DD, dlb + (long)l*3*DD + 2*DD, yo, pAx);
    }
}